// round 12
// baseline (speedup 1.0000x reference)
#include <cuda_runtime.h>
#include <cuda_bf16.h>
#include <cstddef>

// Problem constants
constexpr int Tt   = 512;
constexpr int Bb   = 16;
constexpr int F    = 1024;
constexpr int INP  = 2048;
constexpr int OUTD = 1024;

// ---------------------------------------------------------------------------
// Float/u32 scratch
// ---------------------------------------------------------------------------
constexpr size_t OFF_GX0  = 0;
constexpr size_t SZ_GX    = (size_t)Tt * Bb * 6 * F;
constexpr size_t OFF_GX1  = OFF_GX0 + SZ_GX;
constexpr size_t OFF_OUTT = OFF_GX1 + SZ_GX;
constexpr size_t SZ_OUTT  = (size_t)Tt * Bb * OUTD;
constexpr size_t SZ_WFp   = (size_t)2 * 64 * 6 * 64 * 32 * 2;   // 3145728
constexpr size_t OFF_WFH0 = OFF_OUTT + SZ_OUTT;
constexpr size_t OFF_WFL0 = OFF_WFH0 + SZ_WFp;
constexpr size_t OFF_WFH1 = OFF_WFL0 + SZ_WFp;
constexpr size_t OFF_WFL1 = OFF_WFH1 + SZ_WFp;
constexpr size_t SZ_HF    = (size_t)2 * 2 * 2 * 64 * 32 * 4;    // 65536
constexpr size_t OFF_HF0  = OFF_WFL1 + SZ_WFp;
constexpr size_t OFF_HF1  = OFF_HF0 + SZ_HF;
constexpr size_t OFF_BAR0 = OFF_HF1 + SZ_HF;    // 64 u32 (2 dirs, 128B apart)
constexpr size_t OFF_BAR1 = OFF_BAR0 + 64;
constexpr size_t SCRATCH_TOTAL = OFF_BAR1 + 64;

__device__ float g_scratch[SCRATCH_TOTAL];

// ---------------------------------------------------------------------------
// bf16 scratch (hi/lo planes)
// ---------------------------------------------------------------------------
constexpr size_t SZ_Xe   = (size_t)Tt * Bb * INP;
constexpr size_t SZ_H0e  = (size_t)Tt * Bb * F;
constexpr size_t SZ_Ye   = (size_t)Tt * Bb * 2 * F;
constexpr size_t SZ_WINe = (size_t)F * INP;
constexpr size_t SZ_WI0e = (size_t)6 * F * F;
constexpr size_t SZ_WI1e = (size_t)6 * F * 2 * F;
constexpr size_t SZ_WOe  = (size_t)OUTD * 2 * F;

constexpr size_t BOFF_XH  = 0;
constexpr size_t BOFF_XL  = BOFF_XH  + SZ_Xe;
constexpr size_t BOFF_H0H = BOFF_XL  + SZ_Xe;
constexpr size_t BOFF_H0L = BOFF_H0H + SZ_H0e;
constexpr size_t BOFF_Y0H = BOFF_H0L + SZ_H0e;
constexpr size_t BOFF_Y0L = BOFF_Y0H + SZ_Ye;
constexpr size_t BOFF_Y1H = BOFF_Y0L + SZ_Ye;
constexpr size_t BOFF_Y1L = BOFF_Y1H + SZ_Ye;
constexpr size_t BOFF_WINH= BOFF_Y1L + SZ_Ye;
constexpr size_t BOFF_WINL= BOFF_WINH+ SZ_WINe;
constexpr size_t BOFF_WI0H= BOFF_WINL+ SZ_WINe;
constexpr size_t BOFF_WI0L= BOFF_WI0H+ SZ_WI0e;
constexpr size_t BOFF_WI1H= BOFF_WI0L+ SZ_WI0e;
constexpr size_t BOFF_WI1L= BOFF_WI1H+ SZ_WI1e;
constexpr size_t BOFF_WOH = BOFF_WI1L+ SZ_WI1e;
constexpr size_t BOFF_WOL = BOFF_WOH + SZ_WOe;
constexpr size_t BF_TOTAL = BOFF_WOL + SZ_WOe;

__device__ __nv_bfloat16 g_bf[BF_TOTAL];

// ---------------------------------------------------------------------------
__device__ __forceinline__ void split_store(float v, __nv_bfloat16* h, __nv_bfloat16* l) {
    __nv_bfloat16 hi = __float2bfloat16(v);
    *h = hi;
    *l = __float2bfloat16(v - __bfloat162float(hi));
}

// ---------------------------------------------------------------------------
// Mega-prep kernel: weight splits + W_hh prepacks + HF/BAR zero + input T/split
// ---------------------------------------------------------------------------
constexpr size_t WSPLIT_N  = SZ_WINe + SZ_WI0e + SZ_WI1e + SZ_WOe;
constexpr int NB_WSPLIT  = (int)(WSPLIT_N / 256);
constexpr int NB_PREPACK = (int)(SZ_WFp / 256);
constexpr int NB_ZERO    = 514;
constexpr int NB_TRANS   = (Tt / 32) * (INP / 32) * Bb;
constexpr int NB_PREP    = NB_WSPLIT + 2 * NB_PREPACK + NB_ZERO + NB_TRANS;

__device__ __forceinline__ void prepack_one(const float* __restrict__ whh,
                                            unsigned* __restrict__ wfh,
                                            unsigned* __restrict__ wfl, size_t i)
{
    size_t i2 = i;
    int r   = (int)(i2 & 1);  i2 >>= 1;
    int l   = (int)(i2 & 31); i2 >>= 5;
    int ks  = (int)(i2 & 63); i2 >>= 6;
    int t   = (int)(i2 % 6);  i2 /= 6;
    int blk = (int)(i2 & 63); i2 >>= 6;
    int d   = (int)i2;
    int g = t >> 1, half = t & 1;
    int row = g * 1024 + blk * 16 + half * 8 + (l >> 2);
    int k   = ks * 16 + r * 8 + (l & 3) * 2;
    float w0 = whh[((size_t)d * 3072 + row) * 1024 + k];
    float w1 = whh[((size_t)d * 3072 + row) * 1024 + k + 1];
    __nv_bfloat16 h0 = __float2bfloat16(w0);
    __nv_bfloat16 h1 = __float2bfloat16(w1);
    __nv_bfloat16 l0 = __float2bfloat16(w0 - __bfloat162float(h0));
    __nv_bfloat16 l1 = __float2bfloat16(w1 - __bfloat162float(h1));
    wfh[i] = ((unsigned)__bfloat16_as_ushort(h1) << 16) | (unsigned)__bfloat16_as_ushort(h0);
    wfl[i] = ((unsigned)__bfloat16_as_ushort(l1) << 16) | (unsigned)__bfloat16_as_ushort(l0);
}

__global__ void __launch_bounds__(256) prep_kernel(
    const float* __restrict__ inp,
    const float* __restrict__ w_in, const float* __restrict__ w_ih_l0,
    const float* __restrict__ w_ih_l1, const float* __restrict__ w_out,
    const float* __restrict__ whh0, const float* __restrict__ whh1,
    __nv_bfloat16* __restrict__ BF,
    unsigned* __restrict__ WFH0, unsigned* __restrict__ WFL0,
    unsigned* __restrict__ WFH1, unsigned* __restrict__ WFL1,
    unsigned* __restrict__ HF0, unsigned* __restrict__ HF1,
    unsigned* __restrict__ BAR0, unsigned* __restrict__ BAR1)
{
    __shared__ float tile[32][33];
    int bid = blockIdx.x;
    int tid = threadIdx.x;

    if (bid < NB_WSPLIT) {
        size_t i = (size_t)bid * 256 + tid;
        const float* src; size_t hoff, loff, idx;
        if (i < SZ_WINe) {
            src = w_in; idx = i; hoff = BOFF_WINH + i; loff = BOFF_WINL + i;
        } else if (i < SZ_WINe + SZ_WI0e) {
            idx = i - SZ_WINe; src = w_ih_l0; hoff = BOFF_WI0H + idx; loff = BOFF_WI0L + idx;
        } else if (i < SZ_WINe + SZ_WI0e + SZ_WI1e) {
            idx = i - SZ_WINe - SZ_WI0e; src = w_ih_l1; hoff = BOFF_WI1H + idx; loff = BOFF_WI1L + idx;
        } else {
            idx = i - SZ_WINe - SZ_WI0e - SZ_WI1e; src = w_out; hoff = BOFF_WOH + idx; loff = BOFF_WOL + idx;
        }
        split_store(src[idx], BF + hoff, BF + loff);
        return;
    }
    bid -= NB_WSPLIT;

    if (bid < NB_PREPACK) {
        prepack_one(whh0, WFH0, WFL0, (size_t)bid * 256 + tid);
        return;
    }
    bid -= NB_PREPACK;

    if (bid < NB_PREPACK) {
        prepack_one(whh1, WFH1, WFL1, (size_t)bid * 256 + tid);
        return;
    }
    bid -= NB_PREPACK;

    if (bid < NB_ZERO) {
        size_t i = (size_t)bid * 256 + tid;
        if (i < SZ_HF) HF0[i] = 0;
        else if (i < 2 * SZ_HF) HF1[i - SZ_HF] = 0;
        else if (i < 2 * SZ_HF + 64) BAR0[i - 2 * SZ_HF] = 0;
        else if (i < 2 * SZ_HF + 128) BAR1[i - 2 * SZ_HF - 64] = 0;
        return;
    }
    bid -= NB_ZERO;

    // Input transpose + split
    {
        int b   = bid >> 10;
        int rem = bid & 1023;
        int i0  = (rem >> 4) * 32;
        int t0  = (rem & 15) * 32;
        int tx = tid & 31, ty = tid >> 5;
#pragma unroll
        for (int j = 0; j < 32; j += 8)
            tile[ty + j][tx] = inp[((size_t)b * INP + (i0 + ty + j)) * Tt + t0 + tx];
        __syncthreads();
        __nv_bfloat16* XH = BF + BOFF_XH;
        __nv_bfloat16* XL = BF + BOFF_XL;
#pragma unroll
        for (int j = 0; j < 32; j += 8) {
            size_t o = ((size_t)(t0 + ty + j) * Bb + b) * INP + i0 + tx;
            split_store(tile[tx][ty + j], XH + o, XL + o);
        }
    }
}

__global__ void transpose_out_kernel(const float* __restrict__ in, float* __restrict__ out) {
    __shared__ float tile[32][33];
    int b  = blockIdx.z;
    int t0 = blockIdx.x * 32;
    int o0 = blockIdx.y * 32;
    int tx = threadIdx.x, ty = threadIdx.y;
#pragma unroll
    for (int j = 0; j < 32; j += 8)
        tile[ty + j][tx] = in[((size_t)(t0 + ty + j) * Bb + b) * OUTD + o0 + tx];
    __syncthreads();
#pragma unroll
    for (int j = 0; j < 32; j += 8)
        out[((size_t)b * OUTD + (o0 + ty + j)) * Tt + t0 + tx] = tile[tx][ty + j];
}

// ---------------------------------------------------------------------------
// Tensor-core split-bf16 GEMM; 256x128 tile, BK=32, 1 CTA/SM, 120KB smem.
// Warp grid 4(m) x 2(n), warp tile 64x64.
// ---------------------------------------------------------------------------
constexpr int TW   = 40;             // bf16 stride per smem row
constexpr int PLA  = 256 * TW;       // A plane (bf16 units)
constexpr int PLB  = 128 * TW;       // W plane
constexpr int GBUF = 2 * PLA + 2 * PLB;              // per-buffer bf16 units
constexpr int SMEM_GEMM = 2 * GBUF * (int)sizeof(__nv_bfloat16);  // 122880

__device__ __forceinline__ void cpa16(void* sdst, const void* gsrc) {
    unsigned s = (unsigned)__cvta_generic_to_shared(sdst);
    asm volatile("cp.async.cg.shared.global [%0], [%1], 16;\n" :: "r"(s), "l"(gsrc));
}
__device__ __forceinline__ void cpa_commit() {
    asm volatile("cp.async.commit_group;\n" ::);
}
__device__ __forceinline__ void cpa_wait0() {
    asm volatile("cp.async.wait_group 0;\n" ::);
}
__device__ __forceinline__ void mma_bf16(float* c, const unsigned* a, const unsigned* b) {
    asm volatile(
        "mma.sync.aligned.m16n8k16.row.col.f32.bf16.bf16.f32 "
        "{%0,%1,%2,%3},{%4,%5,%6,%7},{%8,%9},{%0,%1,%2,%3};\n"
        : "+f"(c[0]), "+f"(c[1]), "+f"(c[2]), "+f"(c[3])
        : "r"(a[0]), "r"(a[1]), "r"(a[2]), "r"(a[3]), "r"(b[0]), "r"(b[1]));
}
__device__ __forceinline__ void ldsm4(unsigned* r, const __nv_bfloat16* p) {
    unsigned a = (unsigned)__cvta_generic_to_shared(p);
    asm volatile("ldmatrix.sync.aligned.m8n8.x4.shared.b16 {%0,%1,%2,%3},[%4];\n"
        : "=r"(r[0]), "=r"(r[1]), "=r"(r[2]), "=r"(r[3]) : "r"(a));
}
__device__ __forceinline__ void ldsm2(unsigned* r, const __nv_bfloat16* p) {
    unsigned a = (unsigned)__cvta_generic_to_shared(p);
    asm volatile("ldmatrix.sync.aligned.m8n8.x2.shared.b16 {%0,%1},[%2];\n"
        : "=r"(r[0]), "=r"(r[1]) : "r"(a));
}

__global__ void __launch_bounds__(256, 1) gemm_bf16_split_kernel(
    const __nv_bfloat16* __restrict__ Ah, const __nv_bfloat16* __restrict__ Al,
    const __nv_bfloat16* __restrict__ Wh, const __nv_bfloat16* __restrict__ Wl,
    const float* __restrict__ bias,
    float* __restrict__ C,
    __nv_bfloat16* __restrict__ CH, __nv_bfloat16* __restrict__ CL,
    int M, int N, int K)
{
    extern __shared__ __nv_bfloat16 smx[];
    const int tid = threadIdx.x;
    const int bm = blockIdx.y * 256, bn = blockIdx.x * 128;
    const int lane = tid & 31, wid = tid >> 5;
    const int wm = wid & 3, wn = wid >> 2;
    const int g = lane >> 2, t = lane & 3;

    float acc[4][8][4];
#pragma unroll
    for (int i = 0; i < 4; ++i)
#pragma unroll
        for (int j = 0; j < 8; ++j)
#pragma unroll
            for (int q = 0; q < 4; ++q) acc[i][j][q] = 0.f;

    const int r0 = tid >> 2;            // staging row 0..63
    const int c0 = (tid & 3) * 8;       // staging bf16 col (0/8/16/24)
    const int nk = K / 32;

    // ldmatrix per-lane base offsets (bf16 units)
    const int aOff = (wm * 64 + (lane & 7) + ((lane >> 3) & 1) * 8) * TW + (lane >> 4) * 8;
    const int lb = lane & 15;
    const int bOff = (wn * 64 + (lb & 7)) * TW + ((lb >> 3) & 1) * 8;

    auto stage = [&](__nv_bfloat16* s, int k0) {
        // A planes: 256 rows
#pragma unroll
        for (int p = 0; p < 4; ++p) {
            int row = r0 + p * 64;
            size_t ga = (size_t)(bm + row) * K + k0 + c0;
            int so = row * TW + c0;
            cpa16(s + so, Ah + ga);
            cpa16(s + PLA + so, Al + ga);
        }
        // W planes: 128 rows
#pragma unroll
        for (int p = 0; p < 2; ++p) {
            int row = r0 + p * 64;
            size_t gw = (size_t)(bn + row) * K + k0 + c0;
            int so = row * TW + c0;
            cpa16(s + 2 * PLA + so, Wh + gw);
            cpa16(s + 2 * PLA + PLB + so, Wl + gw);
        }
        cpa_commit();
    };

    stage(smx, 0);

    for (int kt = 0; kt < nk; ++kt) {
        cpa_wait0();
        __syncthreads();

        if (kt + 1 < nk)
            stage(smx + ((kt + 1) & 1) * GBUF, (kt + 1) * 32);

        const __nv_bfloat16* sb = smx + (kt & 1) * GBUF;
        const __nv_bfloat16* sAh = sb;
        const __nv_bfloat16* sAl = sb + PLA;
        const __nv_bfloat16* sWh = sb + 2 * PLA;
        const __nv_bfloat16* sWl = sb + 2 * PLA + PLB;

#pragma unroll
        for (int ks = 0; ks < 2; ++ks) {
            unsigned aH[4][4], aL[4][4], bH[8][2], bL[8][2];
#pragma unroll
            for (int i = 0; i < 4; ++i) {
                int off = aOff + i * 16 * TW + ks * 16;
                ldsm4(aH[i], sAh + off);
                ldsm4(aL[i], sAl + off);
            }
#pragma unroll
            for (int j = 0; j < 8; ++j) {
                int off = bOff + j * 8 * TW + ks * 16;
                ldsm2(bH[j], sWh + off);
                ldsm2(bL[j], sWl + off);
            }
#pragma unroll
            for (int i = 0; i < 4; ++i)
#pragma unroll
                for (int j = 0; j < 8; ++j) {
                    mma_bf16(acc[i][j], aH[i], bH[j]);
                    mma_bf16(acc[i][j], aH[i], bL[j]);
                    mma_bf16(acc[i][j], aL[i], bH[j]);
                }
        }
    }

    // Epilogue
#pragma unroll
    for (int i = 0; i < 4; ++i) {
        int row0 = bm + wm * 64 + i * 16 + g;
#pragma unroll
        for (int j = 0; j < 8; ++j) {
            int col = bn + wn * 64 + j * 8 + t * 2;
            float b0 = bias[col], b1 = bias[col + 1];
            float v00 = acc[i][j][0] + b0, v01 = acc[i][j][1] + b1;
            float v10 = acc[i][j][2] + b0, v11 = acc[i][j][3] + b1;
            if (CH) {
                size_t p0 = (size_t)row0 * N + col;
                size_t p1 = (size_t)(row0 + 8) * N + col;
                __nv_bfloat16 h00 = __float2bfloat16(v00), h01 = __float2bfloat16(v01);
                __nv_bfloat16 h10 = __float2bfloat16(v10), h11 = __float2bfloat16(v11);
                *(__nv_bfloat162*)(CH + p0) = __nv_bfloat162(h00, h01);
                *(__nv_bfloat162*)(CH + p1) = __nv_bfloat162(h10, h11);
                *(__nv_bfloat162*)(CL + p0) = __nv_bfloat162(
                    __float2bfloat16(v00 - __bfloat162float(h00)),
                    __float2bfloat16(v01 - __bfloat162float(h01)));
                *(__nv_bfloat162*)(CL + p1) = __nv_bfloat162(
                    __float2bfloat16(v10 - __bfloat162float(h10)),
                    __float2bfloat16(v11 - __bfloat162float(h11)));
            } else {
                *(float2*)(C + (size_t)row0 * N + col) = make_float2(v00, v01);
                *(float2*)(C + (size_t)(row0 + 8) * N + col) = make_float2(v10, v11);
            }
        }
    }
}

// ---------------------------------------------------------------------------
// Persistent tensor-core bidirectional GRU layer (R7 protocol: tid0-only
// arrive+poll, two syncthreads per step) with MUFU gate math.
// 256 blocks (128/dir), 8 units/block, 2 CTAs/SM. W-hi in regs, W-lo in smem.
// ---------------------------------------------------------------------------
constexpr int WSL_U32 = 3 * 64 * 32 * 2;
constexpr int REC_SMEM = WSL_U32 * 4 + (8 * 3 * 32 * 4) * 4;

__device__ __forceinline__ unsigned ld_acquire(const unsigned* p) {
    unsigned v;
    asm volatile("ld.global.acquire.gpu.u32 %0, [%1];" : "=r"(v) : "l"(p) : "memory");
    return v;
}
__device__ __forceinline__ void red_release_add(unsigned* p, unsigned v) {
    asm volatile("red.release.gpu.global.add.u32 [%0], %1;" :: "l"(p), "r"(v) : "memory");
}
__device__ __forceinline__ float fast_sigmoid(float x) {
    return 1.f / (1.f + __expf(-x));
}
__device__ __forceinline__ float fast_tanh(float x) {
    float e = __expf(2.f * x);
    return (e - 1.f) / (e + 1.f);
}

__global__ void __launch_bounds__(256, 2) gru_layer_tc_kernel(
    const unsigned* __restrict__ WFH, const unsigned* __restrict__ WFL,
    const float* __restrict__ bhh,
    const float* __restrict__ gx,
    __nv_bfloat16* __restrict__ YH, __nv_bfloat16* __restrict__ YL,
    unsigned* __restrict__ HF,
    unsigned* __restrict__ bar)
{
    extern __shared__ unsigned smu[];
    unsigned* wsL = smu;
    float* red = (float*)(smu + WSL_U32);

    const int tid  = threadIdx.x;
    const int dir  = blockIdx.x >> 7;
    const int blk  = blockIdx.x & 127;
    const int B16  = blk >> 1;
    const int half = blk & 1;
    const int u0   = blk * 8;
    const int lane = tid & 31, w = tid >> 5;
    unsigned* bard = bar + dir * 32;

    {
        const unsigned* lbase = WFL + (size_t)(dir * 64 + B16) * (6 * 4096);
#pragma unroll
        for (int t = 0; t < 3; ++t) {
            const uint4* src = (const uint4*)(lbase + (t * 2 + half) * 4096);
            uint4* dst = (uint4*)(wsL + t * 4096);
            for (int i = tid; i < 1024; i += 256) dst[i] = src[i];
        }
    }

    unsigned bHreg[8][3][2];
    {
        const unsigned* hbase = WFH + (size_t)(dir * 64 + B16) * (6 * 4096);
#pragma unroll
        for (int kk = 0; kk < 8; ++kk) {
            int ks = w * 8 + kk;
#pragma unroll
            for (int t = 0; t < 3; ++t) {
                uint2 v = *(const uint2*)(hbase + (t * 2 + half) * 4096 + ks * 64 + lane * 2);
                bHreg[kk][t][0] = v.x;
                bHreg[kk][t][1] = v.y;
            }
        }
    }

    const bool gactive = tid < 128;
    const int gb = tid >> 3;
    const int gu = tid & 7;
    const int gj = u0 + gu;
    float br = 0.f, bz = 0.f, bn2 = 0.f;
    if (gactive) {
        br  = bhh[dir * 3072 + gj];
        bz  = bhh[dir * 3072 + 1024 + gj];
        bn2 = bhh[dir * 3072 + 2048 + gj];
    }
    float hprev = 0.f;

    const int ksb   = blk >> 1;
    const int wlane = ((gb & 7) << 2) + (gu >> 1);
    const int wreg  = (half ? 2 : 0) + ((gb >= 8) ? 1 : 0);
    const int widx  = (ksb * 32 + wlane) * 4 + wreg;
    const int foff  = wlane * 4 + (gu & 1) + ((gb >= 8) ? 2 : 0);

    float xr = 0.f, xz = 0.f, xn = 0.f;
    if (gactive) {
        int tt0 = dir ? (Tt - 1) : 0;
        const float* gxp = gx + (size_t)(tt0 * 16 + gb) * 6144 + dir * 3072;
        xr = __ldg(gxp + gj);
        xz = __ldg(gxp + 1024 + gj);
        xn = __ldg(gxp + 2048 + gj);
    }

    __syncthreads();

    for (int s = 0; s < Tt; ++s) {
        const int cur = s & 1, nxt = cur ^ 1;
        const int tt  = dir ? (Tt - 1 - s) : s;

        float acc[3][4];
#pragma unroll
        for (int t = 0; t < 3; ++t)
#pragma unroll
            for (int q = 0; q < 4; ++q) acc[t][q] = 0.f;

        const unsigned* hfH = HF + ((size_t)(cur * 2 + dir) * 2 + 0) * 8192;
        const unsigned* hfL = HF + ((size_t)(cur * 2 + dir) * 2 + 1) * 8192;

#pragma unroll
        for (int kk = 0; kk < 8; ++kk) {
            int ks = w * 8 + kk;
            uint4 AHv = __ldcg((const uint4*)(hfH + (ks * 32 + lane) * 4));
            uint4 ALv = __ldcg((const uint4*)(hfL + (ks * 32 + lane) * 4));
            unsigned aH[4] = {AHv.x, AHv.y, AHv.z, AHv.w};
            unsigned aL[4] = {ALv.x, ALv.y, ALv.z, ALv.w};
#pragma unroll
            for (int t = 0; t < 3; ++t) {
                uint2 bLv = *(const uint2*)&wsL[t * 4096 + ks * 64 + lane * 2];
                unsigned bL[2] = {bLv.x, bLv.y};
                mma_bf16(acc[t], aH, bHreg[kk][t]);
                mma_bf16(acc[t], aL, bHreg[kk][t]);
                mma_bf16(acc[t], aH, bL);
            }
        }
#pragma unroll
        for (int t = 0; t < 3; ++t)
            *(float4*)&red[((w * 3 + t) * 32 + lane) * 4] =
                make_float4(acc[t][0], acc[t][1], acc[t][2], acc[t][3]);
        __syncthreads();

        if (gactive) {
            float ghr = br, ghz = bz, ghn = bn2;
#pragma unroll
            for (int ww = 0; ww < 8; ++ww) {
                ghr += red[(ww * 3 + 0) * 128 + foff];
                ghz += red[(ww * 3 + 1) * 128 + foff];
                ghn += red[(ww * 3 + 2) * 128 + foff];
            }
            float r = fast_sigmoid(xr + ghr);
            float z = fast_sigmoid(xz + ghz);
            float n = fast_tanh(xn + r * ghn);
            float hnew = (1.f - z) * n + z * hprev;
            hprev = hnew;

            __nv_bfloat16 hhi = __float2bfloat16(hnew);
            float rlo = hnew - __bfloat162float(hhi);
            __nv_bfloat16 hlo = __float2bfloat16(rlo);
            unsigned vh = (unsigned)__bfloat16_as_ushort(hhi);
            unsigned vl = (unsigned)__bfloat16_as_ushort(hlo);
            unsigned phh = __shfl_down_sync(0xffffffffu, vh, 1);
            unsigned pll = __shfl_down_sync(0xffffffffu, vl, 1);
            if ((gu & 1) == 0) {
                unsigned hp = (phh << 16) | vh;
                unsigned lp = (pll << 16) | vl;
                unsigned* oH = HF + ((size_t)(nxt * 2 + dir) * 2 + 0) * 8192;
                unsigned* oL = HF + ((size_t)(nxt * 2 + dir) * 2 + 1) * 8192;
                oH[widx] = hp;
                oL[widx] = lp;
                size_t yi = (size_t)(tt * 16 + gb) * 1024 + dir * 512 + (gj >> 1);
                ((unsigned*)YH)[yi] = hp;
                ((unsigned*)YL)[yi] = lp;
            }

            if (s + 1 < Tt) {
                int ttn = dir ? (Tt - 2 - s) : (s + 1);
                const float* gxn = gx + (size_t)(ttn * 16 + gb) * 6144 + dir * 3072;
                xr = __ldg(gxn + gj);
                xz = __ldg(gxn + 1024 + gj);
                xn = __ldg(gxn + 2048 + gj);
            }
        }

        __syncthreads();
        if (tid == 0) {
            red_release_add(bard, 1u);
            unsigned tgt = (unsigned)(s + 1) * 128;
            while (ld_acquire(bard) < tgt) { }
        }
        __syncthreads();
    }
}

// ---------------------------------------------------------------------------
extern "C" void kernel_launch(void* const* d_in, const int* in_sizes, int n_in,
                              void* d_out, int out_size)
{
    const float* inp     = (const float*)d_in[0];
    const float* w_in    = (const float*)d_in[1];
    const float* b_in    = (const float*)d_in[2];
    const float* w_ih_l0 = (const float*)d_in[3];
    const float* w_hh_l0 = (const float*)d_in[4];
    const float* b_ih_l0 = (const float*)d_in[5];
    const float* b_hh_l0 = (const float*)d_in[6];
    const float* w_ih_l1 = (const float*)d_in[7];
    const float* w_hh_l1 = (const float*)d_in[8];
    const float* b_ih_l1 = (const float*)d_in[9];
    const float* b_hh_l1 = (const float*)d_in[10];
    const float* w_out   = (const float*)d_in[11];
    const float* b_out   = (const float*)d_in[12];
    float* out = (float*)d_out;

    float* S = nullptr;
    cudaGetSymbolAddress((void**)&S, g_scratch);
    __nv_bfloat16* BF = nullptr;
    cudaGetSymbolAddress((void**)&BF, g_bf);

    float* GX0  = S + OFF_GX0;
    float* GX1  = S + OFF_GX1;
    float* OUTT = S + OFF_OUTT;
    unsigned* WFH0 = (unsigned*)(S + OFF_WFH0);
    unsigned* WFL0 = (unsigned*)(S + OFF_WFL0);
    unsigned* WFH1 = (unsigned*)(S + OFF_WFH1);
    unsigned* WFL1 = (unsigned*)(S + OFF_WFL1);
    unsigned* HF0  = (unsigned*)(S + OFF_HF0);
    unsigned* HF1  = (unsigned*)(S + OFF_HF1);
    unsigned* BAR0 = (unsigned*)(S + OFF_BAR0);
    unsigned* BAR1 = (unsigned*)(S + OFF_BAR1);

    cudaFuncSetAttribute(gemm_bf16_split_kernel,
                         cudaFuncAttributeMaxDynamicSharedMemorySize, SMEM_GEMM);
    cudaFuncSetAttribute(gru_layer_tc_kernel,
                         cudaFuncAttributeMaxDynamicSharedMemorySize, REC_SMEM);

    const int M = Tt * Bb;  // 8192

    // 1) Mega-prep
    prep_kernel<<<NB_PREP, 256>>>(inp, w_in, w_ih_l0, w_ih_l1, w_out,
                                  w_hh_l0, w_hh_l1, BF,
                                  WFH0, WFL0, WFH1, WFL1, HF0, HF1, BAR0, BAR1);

    // 2) Input projection (bf16 split output)
    gemm_bf16_split_kernel<<<dim3(F / 128, M / 256), 256, SMEM_GEMM>>>(
        BF + BOFF_XH, BF + BOFF_XL, BF + BOFF_WINH, BF + BOFF_WINL, b_in,
        nullptr, BF + BOFF_H0H, BF + BOFF_H0L, M, F, INP);

    // 3) Layer 0 gx
    gemm_bf16_split_kernel<<<dim3(6 * F / 128, M / 256), 256, SMEM_GEMM>>>(
        BF + BOFF_H0H, BF + BOFF_H0L, BF + BOFF_WI0H, BF + BOFF_WI0L, b_ih_l0,
        GX0, nullptr, nullptr, M, 6 * F, F);

    // 4) Layer 0 recurrence  <-- ncu capture slot
    gru_layer_tc_kernel<<<256, 256, REC_SMEM>>>(
        WFH0, WFL0, b_hh_l0, GX0, BF + BOFF_Y0H, BF + BOFF_Y0L, HF0, BAR0);

    // 5) Layer 1 gx
    gemm_bf16_split_kernel<<<dim3(6 * F / 128, M / 256), 256, SMEM_GEMM>>>(
        BF + BOFF_Y0H, BF + BOFF_Y0L, BF + BOFF_WI1H, BF + BOFF_WI1L, b_ih_l1,
        GX1, nullptr, nullptr, M, 6 * F, 2 * F);

    // 6) Layer 1 recurrence
    gru_layer_tc_kernel<<<256, 256, REC_SMEM>>>(
        WFH1, WFL1, b_hh_l1, GX1, BF + BOFF_Y1H, BF + BOFF_Y1L, HF1, BAR1);

    // 7) Output projection
    gemm_bf16_split_kernel<<<dim3(OUTD / 128, M / 256), 256, SMEM_GEMM>>>(
        BF + BOFF_Y1H, BF + BOFF_Y1L, BF + BOFF_WOH, BF + BOFF_WOL, b_out,
        OUTT, nullptr, nullptr, M, OUTD, 2 * F);

    // 8) Final transpose
    transpose_out_kernel<<<dim3(Tt / 32, OUTD / 32, Bb), dim3(32, 8)>>>(OUTT, out);
}

// round 13
// speedup vs baseline: 1.0329x; 1.0329x over previous
#include <cuda_runtime.h>
#include <cuda_bf16.h>
#include <cstddef>

// Problem constants
constexpr int Tt   = 512;
constexpr int Bb   = 16;
constexpr int F    = 1024;
constexpr int INP  = 2048;
constexpr int OUTD = 1024;

// ---------------------------------------------------------------------------
// Float/u32 scratch
// ---------------------------------------------------------------------------
constexpr size_t OFF_GX0  = 0;
constexpr size_t SZ_GX    = (size_t)Tt * Bb * 6 * F;
constexpr size_t OFF_GX1  = OFF_GX0 + SZ_GX;
constexpr size_t OFF_OUTT = OFF_GX1 + SZ_GX;
constexpr size_t SZ_OUTT  = (size_t)Tt * Bb * OUTD;
constexpr size_t SZ_WFp   = (size_t)2 * 64 * 6 * 64 * 32 * 2;   // 3145728
constexpr size_t OFF_WFH0 = OFF_OUTT + SZ_OUTT;
constexpr size_t OFF_WFL0 = OFF_WFH0 + SZ_WFp;
constexpr size_t OFF_WFH1 = OFF_WFL0 + SZ_WFp;
constexpr size_t OFF_WFL1 = OFF_WFH1 + SZ_WFp;
constexpr size_t SZ_HF    = (size_t)2 * 2 * 2 * 64 * 32 * 4;    // 65536
constexpr size_t OFF_HF0  = OFF_WFL1 + SZ_WFp;
constexpr size_t OFF_HF1  = OFF_HF0 + SZ_HF;
constexpr size_t OFF_BAR0 = OFF_HF1 + SZ_HF;    // 64 u32 (2 dirs, 128B apart)
constexpr size_t OFF_BAR1 = OFF_BAR0 + 64;
constexpr size_t SCRATCH_TOTAL = OFF_BAR1 + 64;

__device__ float g_scratch[SCRATCH_TOTAL];

// ---------------------------------------------------------------------------
// bf16 scratch (hi/lo planes)
// ---------------------------------------------------------------------------
constexpr size_t SZ_Xe   = (size_t)Tt * Bb * INP;
constexpr size_t SZ_H0e  = (size_t)Tt * Bb * F;
constexpr size_t SZ_Ye   = (size_t)Tt * Bb * 2 * F;
constexpr size_t SZ_WINe = (size_t)F * INP;
constexpr size_t SZ_WI0e = (size_t)6 * F * F;
constexpr size_t SZ_WI1e = (size_t)6 * F * 2 * F;
constexpr size_t SZ_WOe  = (size_t)OUTD * 2 * F;

constexpr size_t BOFF_XH  = 0;
constexpr size_t BOFF_XL  = BOFF_XH  + SZ_Xe;
constexpr size_t BOFF_H0H = BOFF_XL  + SZ_Xe;
constexpr size_t BOFF_H0L = BOFF_H0H + SZ_H0e;
constexpr size_t BOFF_Y0H = BOFF_H0L + SZ_H0e;
constexpr size_t BOFF_Y0L = BOFF_Y0H + SZ_Ye;
constexpr size_t BOFF_Y1H = BOFF_Y0L + SZ_Ye;
constexpr size_t BOFF_Y1L = BOFF_Y1H + SZ_Ye;
constexpr size_t BOFF_WINH= BOFF_Y1L + SZ_Ye;
constexpr size_t BOFF_WINL= BOFF_WINH+ SZ_WINe;
constexpr size_t BOFF_WI0H= BOFF_WINL+ SZ_WINe;
constexpr size_t BOFF_WI0L= BOFF_WI0H+ SZ_WI0e;
constexpr size_t BOFF_WI1H= BOFF_WI0L+ SZ_WI0e;
constexpr size_t BOFF_WI1L= BOFF_WI1H+ SZ_WI1e;
constexpr size_t BOFF_WOH = BOFF_WI1L+ SZ_WI1e;
constexpr size_t BOFF_WOL = BOFF_WOH + SZ_WOe;
constexpr size_t BF_TOTAL = BOFF_WOL + SZ_WOe;

__device__ __nv_bfloat16 g_bf[BF_TOTAL];

// ---------------------------------------------------------------------------
__device__ __forceinline__ void split_store(float v, __nv_bfloat16* h, __nv_bfloat16* l) {
    __nv_bfloat16 hi = __float2bfloat16(v);
    *h = hi;
    *l = __float2bfloat16(v - __bfloat162float(hi));
}

// ---------------------------------------------------------------------------
// Mega-prep kernel: weight splits + W_hh prepacks + HF/BAR zero + input T/split
// ---------------------------------------------------------------------------
constexpr size_t WSPLIT_N  = SZ_WINe + SZ_WI0e + SZ_WI1e + SZ_WOe;
constexpr int NB_WSPLIT  = (int)(WSPLIT_N / 256);
constexpr int NB_PREPACK = (int)(SZ_WFp / 256);
constexpr int NB_ZERO    = 514;
constexpr int NB_TRANS   = (Tt / 32) * (INP / 32) * Bb;
constexpr int NB_PREP    = NB_WSPLIT + 2 * NB_PREPACK + NB_ZERO + NB_TRANS;

__device__ __forceinline__ void prepack_one(const float* __restrict__ whh,
                                            unsigned* __restrict__ wfh,
                                            unsigned* __restrict__ wfl, size_t i)
{
    size_t i2 = i;
    int r   = (int)(i2 & 1);  i2 >>= 1;
    int l   = (int)(i2 & 31); i2 >>= 5;
    int ks  = (int)(i2 & 63); i2 >>= 6;
    int t   = (int)(i2 % 6);  i2 /= 6;
    int blk = (int)(i2 & 63); i2 >>= 6;
    int d   = (int)i2;
    int g = t >> 1, half = t & 1;
    int row = g * 1024 + blk * 16 + half * 8 + (l >> 2);
    int k   = ks * 16 + r * 8 + (l & 3) * 2;
    float w0 = whh[((size_t)d * 3072 + row) * 1024 + k];
    float w1 = whh[((size_t)d * 3072 + row) * 1024 + k + 1];
    __nv_bfloat16 h0 = __float2bfloat16(w0);
    __nv_bfloat16 h1 = __float2bfloat16(w1);
    __nv_bfloat16 l0 = __float2bfloat16(w0 - __bfloat162float(h0));
    __nv_bfloat16 l1 = __float2bfloat16(w1 - __bfloat162float(h1));
    wfh[i] = ((unsigned)__bfloat16_as_ushort(h1) << 16) | (unsigned)__bfloat16_as_ushort(h0);
    wfl[i] = ((unsigned)__bfloat16_as_ushort(l1) << 16) | (unsigned)__bfloat16_as_ushort(l0);
}

__global__ void __launch_bounds__(256) prep_kernel(
    const float* __restrict__ inp,
    const float* __restrict__ w_in, const float* __restrict__ w_ih_l0,
    const float* __restrict__ w_ih_l1, const float* __restrict__ w_out,
    const float* __restrict__ whh0, const float* __restrict__ whh1,
    __nv_bfloat16* __restrict__ BF,
    unsigned* __restrict__ WFH0, unsigned* __restrict__ WFL0,
    unsigned* __restrict__ WFH1, unsigned* __restrict__ WFL1,
    unsigned* __restrict__ HF0, unsigned* __restrict__ HF1,
    unsigned* __restrict__ BAR0, unsigned* __restrict__ BAR1)
{
    __shared__ float tile[32][33];
    int bid = blockIdx.x;
    int tid = threadIdx.x;

    if (bid < NB_WSPLIT) {
        size_t i = (size_t)bid * 256 + tid;
        const float* src; size_t hoff, loff, idx;
        if (i < SZ_WINe) {
            src = w_in; idx = i; hoff = BOFF_WINH + i; loff = BOFF_WINL + i;
        } else if (i < SZ_WINe + SZ_WI0e) {
            idx = i - SZ_WINe; src = w_ih_l0; hoff = BOFF_WI0H + idx; loff = BOFF_WI0L + idx;
        } else if (i < SZ_WINe + SZ_WI0e + SZ_WI1e) {
            idx = i - SZ_WINe - SZ_WI0e; src = w_ih_l1; hoff = BOFF_WI1H + idx; loff = BOFF_WI1L + idx;
        } else {
            idx = i - SZ_WINe - SZ_WI0e - SZ_WI1e; src = w_out; hoff = BOFF_WOH + idx; loff = BOFF_WOL + idx;
        }
        split_store(src[idx], BF + hoff, BF + loff);
        return;
    }
    bid -= NB_WSPLIT;

    if (bid < NB_PREPACK) {
        prepack_one(whh0, WFH0, WFL0, (size_t)bid * 256 + tid);
        return;
    }
    bid -= NB_PREPACK;

    if (bid < NB_PREPACK) {
        prepack_one(whh1, WFH1, WFL1, (size_t)bid * 256 + tid);
        return;
    }
    bid -= NB_PREPACK;

    if (bid < NB_ZERO) {
        size_t i = (size_t)bid * 256 + tid;
        if (i < SZ_HF) HF0[i] = 0;
        else if (i < 2 * SZ_HF) HF1[i - SZ_HF] = 0;
        else if (i < 2 * SZ_HF + 64) BAR0[i - 2 * SZ_HF] = 0;
        else if (i < 2 * SZ_HF + 128) BAR1[i - 2 * SZ_HF - 64] = 0;
        return;
    }
    bid -= NB_ZERO;

    // Input transpose + split
    {
        int b   = bid >> 10;
        int rem = bid & 1023;
        int i0  = (rem >> 4) * 32;
        int t0  = (rem & 15) * 32;
        int tx = tid & 31, ty = tid >> 5;
#pragma unroll
        for (int j = 0; j < 32; j += 8)
            tile[ty + j][tx] = inp[((size_t)b * INP + (i0 + ty + j)) * Tt + t0 + tx];
        __syncthreads();
        __nv_bfloat16* XH = BF + BOFF_XH;
        __nv_bfloat16* XL = BF + BOFF_XL;
#pragma unroll
        for (int j = 0; j < 32; j += 8) {
            size_t o = ((size_t)(t0 + ty + j) * Bb + b) * INP + i0 + tx;
            split_store(tile[tx][ty + j], XH + o, XL + o);
        }
    }
}

__global__ void transpose_out_kernel(const float* __restrict__ in, float* __restrict__ out) {
    __shared__ float tile[32][33];
    int b  = blockIdx.z;
    int t0 = blockIdx.x * 32;
    int o0 = blockIdx.y * 32;
    int tx = threadIdx.x, ty = threadIdx.y;
#pragma unroll
    for (int j = 0; j < 32; j += 8)
        tile[ty + j][tx] = in[((size_t)(t0 + ty + j) * Bb + b) * OUTD + o0 + tx];
    __syncthreads();
#pragma unroll
    for (int j = 0; j < 32; j += 8)
        out[((size_t)b * OUTD + (o0 + ty + j)) * Tt + t0 + tx] = tile[tx][ty + j];
}

// ---------------------------------------------------------------------------
// Tensor-core split-bf16 GEMM; 128x128 tile, 2 CTAs/SM (TW=40, 80KB smem).
// B fragments loaded via paired ldsm4 (lane mapping covers n16xk16).
// ---------------------------------------------------------------------------
constexpr int TW  = 40;
constexpr int PL  = 128 * TW;
constexpr int GBUF = 4 * PL;
constexpr int SMEM_GEMM = 2 * GBUF * (int)sizeof(__nv_bfloat16);  // 81920

__device__ __forceinline__ void cpa16(void* sdst, const void* gsrc) {
    unsigned s = (unsigned)__cvta_generic_to_shared(sdst);
    asm volatile("cp.async.cg.shared.global [%0], [%1], 16;\n" :: "r"(s), "l"(gsrc));
}
__device__ __forceinline__ void cpa_commit() {
    asm volatile("cp.async.commit_group;\n" ::);
}
__device__ __forceinline__ void cpa_wait0() {
    asm volatile("cp.async.wait_group 0;\n" ::);
}
__device__ __forceinline__ void mma_bf16(float* c, const unsigned* a, const unsigned* b) {
    asm volatile(
        "mma.sync.aligned.m16n8k16.row.col.f32.bf16.bf16.f32 "
        "{%0,%1,%2,%3},{%4,%5,%6,%7},{%8,%9},{%0,%1,%2,%3};\n"
        : "+f"(c[0]), "+f"(c[1]), "+f"(c[2]), "+f"(c[3])
        : "r"(a[0]), "r"(a[1]), "r"(a[2]), "r"(a[3]), "r"(b[0]), "r"(b[1]));
}
__device__ __forceinline__ void ldsm4(unsigned* r, const __nv_bfloat16* p) {
    unsigned a = (unsigned)__cvta_generic_to_shared(p);
    asm volatile("ldmatrix.sync.aligned.m8n8.x4.shared.b16 {%0,%1,%2,%3},[%4];\n"
        : "=r"(r[0]), "=r"(r[1]), "=r"(r[2]), "=r"(r[3]) : "r"(a));
}

__global__ void __launch_bounds__(256, 2) gemm_bf16_split_kernel(
    const __nv_bfloat16* __restrict__ Ah, const __nv_bfloat16* __restrict__ Al,
    const __nv_bfloat16* __restrict__ Wh, const __nv_bfloat16* __restrict__ Wl,
    const float* __restrict__ bias,
    float* __restrict__ C,
    __nv_bfloat16* __restrict__ CH, __nv_bfloat16* __restrict__ CL,
    int M, int N, int K)
{
    extern __shared__ __nv_bfloat16 smx[];
    const int tid = threadIdx.x;
    const int bm = blockIdx.y * 128, bn = blockIdx.x * 128;
    const int lane = tid & 31, wid = tid >> 5;
    const int wm = wid & 1, wn = wid >> 1;
    const int g = lane >> 2, t = lane & 3;

    float acc[4][4][4];
#pragma unroll
    for (int i = 0; i < 4; ++i)
#pragma unroll
        for (int j = 0; j < 4; ++j)
#pragma unroll
            for (int q = 0; q < 4; ++q) acc[i][j][q] = 0.f;

    const int r0 = tid >> 2;
    const int c0 = (tid & 3) * 8;
    const int nk = K / 32;

    // A ldsm4 lane offset: rows m..m+15, halves at k0/k8
    const int aOff = (wm * 64 + (lane & 7) + ((lane >> 3) & 1) * 8) * TW + (lane >> 4) * 8;
    // B paired ldsm4 lane offset: lanes 0-7:(n,k0) 8-15:(n,k8) 16-23:(n+8,k0) 24-31:(n+8,k8)
    const int bOff4 = (wn * 32 + (lane & 7) + ((lane >> 4) & 1) * 8) * TW
                    + ((lane >> 3) & 1) * 8;

    {
        __nv_bfloat16* s = smx;
#pragma unroll
        for (int p = 0; p < 2; ++p) {
            int row = r0 + p * 64;
            size_t ga = (size_t)(bm + row) * K + c0;
            size_t gw = (size_t)(bn + row) * K + c0;
            int so = row * TW + c0;
            cpa16(s + 0 * PL + so, Ah + ga);
            cpa16(s + 1 * PL + so, Al + ga);
            cpa16(s + 2 * PL + so, Wh + gw);
            cpa16(s + 3 * PL + so, Wl + gw);
        }
        cpa_commit();
    }

    for (int kt = 0; kt < nk; ++kt) {
        cpa_wait0();
        __syncthreads();

        if (kt + 1 < nk) {
            __nv_bfloat16* s = smx + ((kt + 1) & 1) * GBUF;
            int k0 = (kt + 1) * 32;
#pragma unroll
            for (int p = 0; p < 2; ++p) {
                int row = r0 + p * 64;
                size_t ga = (size_t)(bm + row) * K + k0 + c0;
                size_t gw = (size_t)(bn + row) * K + k0 + c0;
                int so = row * TW + c0;
                cpa16(s + 0 * PL + so, Ah + ga);
                cpa16(s + 1 * PL + so, Al + ga);
                cpa16(s + 2 * PL + so, Wh + gw);
                cpa16(s + 3 * PL + so, Wl + gw);
            }
            cpa_commit();
        }

        const __nv_bfloat16* sb = smx + (kt & 1) * GBUF;

#pragma unroll
        for (int ks = 0; ks < 2; ++ks) {
            unsigned aH[4][4], aL[4][4], bH[4][2], bL[4][2];
#pragma unroll
            for (int i = 0; i < 4; ++i) {
                int off = aOff + i * 16 * TW + ks * 16;
                ldsm4(aH[i], sb + 0 * PL + off);
                ldsm4(aL[i], sb + 1 * PL + off);
            }
#pragma unroll
            for (int j2 = 0; j2 < 2; ++j2) {
                int off = bOff4 + j2 * 16 * TW + ks * 16;
                unsigned tmp[4];
                ldsm4(tmp, sb + 2 * PL + off);
                bH[j2 * 2][0] = tmp[0]; bH[j2 * 2][1] = tmp[1];
                bH[j2 * 2 + 1][0] = tmp[2]; bH[j2 * 2 + 1][1] = tmp[3];
                ldsm4(tmp, sb + 3 * PL + off);
                bL[j2 * 2][0] = tmp[0]; bL[j2 * 2][1] = tmp[1];
                bL[j2 * 2 + 1][0] = tmp[2]; bL[j2 * 2 + 1][1] = tmp[3];
            }
#pragma unroll
            for (int i = 0; i < 4; ++i)
#pragma unroll
                for (int j = 0; j < 4; ++j) {
                    mma_bf16(acc[i][j], aH[i], bH[j]);
                    mma_bf16(acc[i][j], aH[i], bL[j]);
                    mma_bf16(acc[i][j], aL[i], bH[j]);
                }
        }
    }

#pragma unroll
    for (int i = 0; i < 4; ++i) {
        int row0 = bm + wm * 64 + i * 16 + g;
#pragma unroll
        for (int j = 0; j < 4; ++j) {
            int col = bn + wn * 32 + j * 8 + t * 2;
            float b0 = bias[col], b1 = bias[col + 1];
            float v00 = acc[i][j][0] + b0, v01 = acc[i][j][1] + b1;
            float v10 = acc[i][j][2] + b0, v11 = acc[i][j][3] + b1;
            if (CH) {
                size_t p0 = (size_t)row0 * N + col;
                size_t p1 = (size_t)(row0 + 8) * N + col;
                __nv_bfloat16 h00 = __float2bfloat16(v00), h01 = __float2bfloat16(v01);
                __nv_bfloat16 h10 = __float2bfloat16(v10), h11 = __float2bfloat16(v11);
                *(__nv_bfloat162*)(CH + p0) = __nv_bfloat162(h00, h01);
                *(__nv_bfloat162*)(CH + p1) = __nv_bfloat162(h10, h11);
                *(__nv_bfloat162*)(CL + p0) = __nv_bfloat162(
                    __float2bfloat16(v00 - __bfloat162float(h00)),
                    __float2bfloat16(v01 - __bfloat162float(h01)));
                *(__nv_bfloat162*)(CL + p1) = __nv_bfloat162(
                    __float2bfloat16(v10 - __bfloat162float(h10)),
                    __float2bfloat16(v11 - __bfloat162float(h11)));
            } else {
                *(float2*)(C + (size_t)row0 * N + col) = make_float2(v00, v01);
                *(float2*)(C + (size_t)(row0 + 8) * N + col) = make_float2(v10, v11);
            }
        }
    }
}

// ---------------------------------------------------------------------------
// Persistent tensor-core bidirectional GRU layer (R7 protocol, MUFU gates)
// 256 blocks (128/dir), 8 units/block, 2 CTAs/SM. W-hi in regs, W-lo in smem.
// ---------------------------------------------------------------------------
constexpr int WSL_U32 = 3 * 64 * 32 * 2;
constexpr int REC_SMEM = WSL_U32 * 4 + (8 * 3 * 32 * 4) * 4;

__device__ __forceinline__ unsigned ld_acquire(const unsigned* p) {
    unsigned v;
    asm volatile("ld.global.acquire.gpu.u32 %0, [%1];" : "=r"(v) : "l"(p) : "memory");
    return v;
}
__device__ __forceinline__ void red_release_add(unsigned* p, unsigned v) {
    asm volatile("red.release.gpu.global.add.u32 [%0], %1;" :: "l"(p), "r"(v) : "memory");
}
__device__ __forceinline__ float fast_sigmoid(float x) {
    return 1.f / (1.f + __expf(-x));
}
__device__ __forceinline__ float fast_tanh(float x) {
    float e = __expf(2.f * x);
    return (e - 1.f) / (e + 1.f);
}

__global__ void __launch_bounds__(256, 2) gru_layer_tc_kernel(
    const unsigned* __restrict__ WFH, const unsigned* __restrict__ WFL,
    const float* __restrict__ bhh,
    const float* __restrict__ gx,
    __nv_bfloat16* __restrict__ YH, __nv_bfloat16* __restrict__ YL,
    unsigned* __restrict__ HF,
    unsigned* __restrict__ bar)
{
    extern __shared__ unsigned smu[];
    unsigned* wsL = smu;
    float* red = (float*)(smu + WSL_U32);

    const int tid  = threadIdx.x;
    const int dir  = blockIdx.x >> 7;
    const int blk  = blockIdx.x & 127;
    const int B16  = blk >> 1;
    const int half = blk & 1;
    const int u0   = blk * 8;
    const int lane = tid & 31, w = tid >> 5;
    unsigned* bard = bar + dir * 32;

    {
        const unsigned* lbase = WFL + (size_t)(dir * 64 + B16) * (6 * 4096);
#pragma unroll
        for (int t = 0; t < 3; ++t) {
            const uint4* src = (const uint4*)(lbase + (t * 2 + half) * 4096);
            uint4* dst = (uint4*)(wsL + t * 4096);
            for (int i = tid; i < 1024; i += 256) dst[i] = src[i];
        }
    }

    unsigned bHreg[8][3][2];
    {
        const unsigned* hbase = WFH + (size_t)(dir * 64 + B16) * (6 * 4096);
#pragma unroll
        for (int kk = 0; kk < 8; ++kk) {
            int ks = w * 8 + kk;
#pragma unroll
            for (int t = 0; t < 3; ++t) {
                uint2 v = *(const uint2*)(hbase + (t * 2 + half) * 4096 + ks * 64 + lane * 2);
                bHreg[kk][t][0] = v.x;
                bHreg[kk][t][1] = v.y;
            }
        }
    }

    const bool gactive = tid < 128;
    const int gb = tid >> 3;
    const int gu = tid & 7;
    const int gj = u0 + gu;
    float br = 0.f, bz = 0.f, bn2 = 0.f;
    if (gactive) {
        br  = bhh[dir * 3072 + gj];
        bz  = bhh[dir * 3072 + 1024 + gj];
        bn2 = bhh[dir * 3072 + 2048 + gj];
    }
    float hprev = 0.f;

    const int ksb   = blk >> 1;
    const int wlane = ((gb & 7) << 2) + (gu >> 1);
    const int wreg  = (half ? 2 : 0) + ((gb >= 8) ? 1 : 0);
    const int widx  = (ksb * 32 + wlane) * 4 + wreg;
    const int foff  = wlane * 4 + (gu & 1) + ((gb >= 8) ? 2 : 0);

    float xr = 0.f, xz = 0.f, xn = 0.f;
    if (gactive) {
        int tt0 = dir ? (Tt - 1) : 0;
        const float* gxp = gx + (size_t)(tt0 * 16 + gb) * 6144 + dir * 3072;
        xr = __ldg(gxp + gj);
        xz = __ldg(gxp + 1024 + gj);
        xn = __ldg(gxp + 2048 + gj);
    }

    __syncthreads();

    for (int s = 0; s < Tt; ++s) {
        const int cur = s & 1, nxt = cur ^ 1;
        const int tt  = dir ? (Tt - 1 - s) : s;

        float acc[3][4];
#pragma unroll
        for (int t = 0; t < 3; ++t)
#pragma unroll
            for (int q = 0; q < 4; ++q) acc[t][q] = 0.f;

        const unsigned* hfH = HF + ((size_t)(cur * 2 + dir) * 2 + 0) * 8192;
        const unsigned* hfL = HF + ((size_t)(cur * 2 + dir) * 2 + 1) * 8192;

#pragma unroll
        for (int kk = 0; kk < 8; ++kk) {
            int ks = w * 8 + kk;
            uint4 AHv = __ldcg((const uint4*)(hfH + (ks * 32 + lane) * 4));
            uint4 ALv = __ldcg((const uint4*)(hfL + (ks * 32 + lane) * 4));
            unsigned aH[4] = {AHv.x, AHv.y, AHv.z, AHv.w};
            unsigned aL[4] = {ALv.x, ALv.y, ALv.z, ALv.w};
#pragma unroll
            for (int t = 0; t < 3; ++t) {
                uint2 bLv = *(const uint2*)&wsL[t * 4096 + ks * 64 + lane * 2];
                unsigned bL[2] = {bLv.x, bLv.y};
                mma_bf16(acc[t], aH, bHreg[kk][t]);
                mma_bf16(acc[t], aL, bHreg[kk][t]);
                mma_bf16(acc[t], aH, bL);
            }
        }
#pragma unroll
        for (int t = 0; t < 3; ++t)
            *(float4*)&red[((w * 3 + t) * 32 + lane) * 4] =
                make_float4(acc[t][0], acc[t][1], acc[t][2], acc[t][3]);
        __syncthreads();

        if (gactive) {
            float ghr = br, ghz = bz, ghn = bn2;
#pragma unroll
            for (int ww = 0; ww < 8; ++ww) {
                ghr += red[(ww * 3 + 0) * 128 + foff];
                ghz += red[(ww * 3 + 1) * 128 + foff];
                ghn += red[(ww * 3 + 2) * 128 + foff];
            }
            float r = fast_sigmoid(xr + ghr);
            float z = fast_sigmoid(xz + ghz);
            float n = fast_tanh(xn + r * ghn);
            float hnew = (1.f - z) * n + z * hprev;
            hprev = hnew;

            __nv_bfloat16 hhi = __float2bfloat16(hnew);
            float rlo = hnew - __bfloat162float(hhi);
            __nv_bfloat16 hlo = __float2bfloat16(rlo);
            unsigned vh = (unsigned)__bfloat16_as_ushort(hhi);
            unsigned vl = (unsigned)__bfloat16_as_ushort(hlo);
            unsigned phh = __shfl_down_sync(0xffffffffu, vh, 1);
            unsigned pll = __shfl_down_sync(0xffffffffu, vl, 1);
            if ((gu & 1) == 0) {
                unsigned hp = (phh << 16) | vh;
                unsigned lp = (pll << 16) | vl;
                unsigned* oH = HF + ((size_t)(nxt * 2 + dir) * 2 + 0) * 8192;
                unsigned* oL = HF + ((size_t)(nxt * 2 + dir) * 2 + 1) * 8192;
                oH[widx] = hp;
                oL[widx] = lp;
                size_t yi = (size_t)(tt * 16 + gb) * 1024 + dir * 512 + (gj >> 1);
                ((unsigned*)YH)[yi] = hp;
                ((unsigned*)YL)[yi] = lp;
            }

            if (s + 1 < Tt) {
                int ttn = dir ? (Tt - 2 - s) : (s + 1);
                const float* gxn = gx + (size_t)(ttn * 16 + gb) * 6144 + dir * 3072;
                xr = __ldg(gxn + gj);
                xz = __ldg(gxn + 1024 + gj);
                xn = __ldg(gxn + 2048 + gj);
            }
        }

        __syncthreads();
        if (tid == 0) {
            red_release_add(bard, 1u);
            unsigned tgt = (unsigned)(s + 1) * 128;
            while (ld_acquire(bard) < tgt) { }
        }
        __syncthreads();
    }
}

// ---------------------------------------------------------------------------
extern "C" void kernel_launch(void* const* d_in, const int* in_sizes, int n_in,
                              void* d_out, int out_size)
{
    const float* inp     = (const float*)d_in[0];
    const float* w_in    = (const float*)d_in[1];
    const float* b_in    = (const float*)d_in[2];
    const float* w_ih_l0 = (const float*)d_in[3];
    const float* w_hh_l0 = (const float*)d_in[4];
    const float* b_ih_l0 = (const float*)d_in[5];
    const float* b_hh_l0 = (const float*)d_in[6];
    const float* w_ih_l1 = (const float*)d_in[7];
    const float* w_hh_l1 = (const float*)d_in[8];
    const float* b_ih_l1 = (const float*)d_in[9];
    const float* b_hh_l1 = (const float*)d_in[10];
    const float* w_out   = (const float*)d_in[11];
    const float* b_out   = (const float*)d_in[12];
    float* out = (float*)d_out;

    float* S = nullptr;
    cudaGetSymbolAddress((void**)&S, g_scratch);
    __nv_bfloat16* BF = nullptr;
    cudaGetSymbolAddress((void**)&BF, g_bf);

    float* GX0  = S + OFF_GX0;
    float* GX1  = S + OFF_GX1;
    float* OUTT = S + OFF_OUTT;
    unsigned* WFH0 = (unsigned*)(S + OFF_WFH0);
    unsigned* WFL0 = (unsigned*)(S + OFF_WFL0);
    unsigned* WFH1 = (unsigned*)(S + OFF_WFH1);
    unsigned* WFL1 = (unsigned*)(S + OFF_WFL1);
    unsigned* HF0  = (unsigned*)(S + OFF_HF0);
    unsigned* HF1  = (unsigned*)(S + OFF_HF1);
    unsigned* BAR0 = (unsigned*)(S + OFF_BAR0);
    unsigned* BAR1 = (unsigned*)(S + OFF_BAR1);

    cudaFuncSetAttribute(gemm_bf16_split_kernel,
                         cudaFuncAttributeMaxDynamicSharedMemorySize, SMEM_GEMM);
    cudaFuncSetAttribute(gru_layer_tc_kernel,
                         cudaFuncAttributeMaxDynamicSharedMemorySize, REC_SMEM);

    const int M = Tt * Bb;  // 8192

    // 1) Mega-prep
    prep_kernel<<<NB_PREP, 256>>>(inp, w_in, w_ih_l0, w_ih_l1, w_out,
                                  w_hh_l0, w_hh_l1, BF,
                                  WFH0, WFL0, WFH1, WFL1, HF0, HF1, BAR0, BAR1);

    // 2) Input projection (bf16 split output)
    gemm_bf16_split_kernel<<<dim3(F / 128, M / 128), 256, SMEM_GEMM>>>(
        BF + BOFF_XH, BF + BOFF_XL, BF + BOFF_WINH, BF + BOFF_WINL, b_in,
        nullptr, BF + BOFF_H0H, BF + BOFF_H0L, M, F, INP);

    // 3) Layer 0 gx
    gemm_bf16_split_kernel<<<dim3(6 * F / 128, M / 128), 256, SMEM_GEMM>>>(
        BF + BOFF_H0H, BF + BOFF_H0L, BF + BOFF_WI0H, BF + BOFF_WI0L, b_ih_l0,
        GX0, nullptr, nullptr, M, 6 * F, F);

    // 4) Layer 0 recurrence  <-- ncu capture slot
    gru_layer_tc_kernel<<<256, 256, REC_SMEM>>>(
        WFH0, WFL0, b_hh_l0, GX0, BF + BOFF_Y0H, BF + BOFF_Y0L, HF0, BAR0);

    // 5) Layer 1 gx
    gemm_bf16_split_kernel<<<dim3(6 * F / 128, M / 128), 256, SMEM_GEMM>>>(
        BF + BOFF_Y0H, BF + BOFF_Y0L, BF + BOFF_WI1H, BF + BOFF_WI1L, b_ih_l1,
        GX1, nullptr, nullptr, M, 6 * F, 2 * F);

    // 6) Layer 1 recurrence
    gru_layer_tc_kernel<<<256, 256, REC_SMEM>>>(
        WFH1, WFL1, b_hh_l1, GX1, BF + BOFF_Y1H, BF + BOFF_Y1L, HF1, BAR1);

    // 7) Output projection
    gemm_bf16_split_kernel<<<dim3(OUTD / 128, M / 128), 256, SMEM_GEMM>>>(
        BF + BOFF_Y1H, BF + BOFF_Y1L, BF + BOFF_WOH, BF + BOFF_WOL, b_out,
        OUTT, nullptr, nullptr, M, OUTD, 2 * F);

    // 8) Final transpose
    transpose_out_kernel<<<dim3(Tt / 32, OUTD / 32, Bb), dim3(32, 8)>>>(OUTT, out);
}

// round 14
// speedup vs baseline: 1.0431x; 1.0099x over previous
#include <cuda_runtime.h>
#include <cuda_bf16.h>
#include <cstddef>

// Problem constants
constexpr int Tt   = 512;
constexpr int Bb   = 16;
constexpr int F    = 1024;
constexpr int INP  = 2048;
constexpr int OUTD = 1024;

// ---------------------------------------------------------------------------
// Float/u32 scratch
// ---------------------------------------------------------------------------
constexpr size_t OFF_GX0  = 0;
constexpr size_t SZ_GX    = (size_t)Tt * Bb * 6 * F;
constexpr size_t OFF_GX1  = OFF_GX0 + SZ_GX;
constexpr size_t OFF_OUTT = OFF_GX1 + SZ_GX;
constexpr size_t SZ_OUTT  = (size_t)Tt * Bb * OUTD;
constexpr size_t SZ_WFp   = (size_t)2 * 64 * 6 * 64 * 32 * 2;   // 3145728
constexpr size_t OFF_WFH0 = OFF_OUTT + SZ_OUTT;
constexpr size_t OFF_WFL0 = OFF_WFH0 + SZ_WFp;
constexpr size_t OFF_WFH1 = OFF_WFL0 + SZ_WFp;
constexpr size_t OFF_WFL1 = OFF_WFH1 + SZ_WFp;
constexpr size_t SZ_HF    = (size_t)2 * 2 * 2 * 64 * 32 * 4;    // 65536
constexpr size_t OFF_HF0  = OFF_WFL1 + SZ_WFp;
constexpr size_t OFF_HF1  = OFF_HF0 + SZ_HF;
constexpr size_t OFF_BAR0 = OFF_HF1 + SZ_HF;    // 64 u32 (2 dirs, 128B apart)
constexpr size_t OFF_BAR1 = OFF_BAR0 + 64;
constexpr size_t SCRATCH_TOTAL = OFF_BAR1 + 64;

__device__ float g_scratch[SCRATCH_TOTAL];

// ---------------------------------------------------------------------------
// bf16 scratch (hi/lo planes)
// ---------------------------------------------------------------------------
constexpr size_t SZ_Xe   = (size_t)Tt * Bb * INP;
constexpr size_t SZ_H0e  = (size_t)Tt * Bb * F;
constexpr size_t SZ_Ye   = (size_t)Tt * Bb * 2 * F;
constexpr size_t SZ_WINe = (size_t)F * INP;
constexpr size_t SZ_WI0e = (size_t)6 * F * F;
constexpr size_t SZ_WI1e = (size_t)6 * F * 2 * F;
constexpr size_t SZ_WOe  = (size_t)OUTD * 2 * F;

constexpr size_t BOFF_XH  = 0;
constexpr size_t BOFF_XL  = BOFF_XH  + SZ_Xe;
constexpr size_t BOFF_H0H = BOFF_XL  + SZ_Xe;
constexpr size_t BOFF_H0L = BOFF_H0H + SZ_H0e;
constexpr size_t BOFF_Y0H = BOFF_H0L + SZ_H0e;
constexpr size_t BOFF_Y0L = BOFF_Y0H + SZ_Ye;
constexpr size_t BOFF_Y1H = BOFF_Y0L + SZ_Ye;
constexpr size_t BOFF_Y1L = BOFF_Y1H + SZ_Ye;
constexpr size_t BOFF_WINH= BOFF_Y1L + SZ_Ye;
constexpr size_t BOFF_WINL= BOFF_WINH+ SZ_WINe;
constexpr size_t BOFF_WI0H= BOFF_WINL+ SZ_WINe;
constexpr size_t BOFF_WI0L= BOFF_WI0H+ SZ_WI0e;
constexpr size_t BOFF_WI1H= BOFF_WI0L+ SZ_WI0e;
constexpr size_t BOFF_WI1L= BOFF_WI1H+ SZ_WI1e;
constexpr size_t BOFF_WOH = BOFF_WI1L+ SZ_WI1e;
constexpr size_t BOFF_WOL = BOFF_WOH + SZ_WOe;
constexpr size_t BF_TOTAL = BOFF_WOL + SZ_WOe;

__device__ __nv_bfloat16 g_bf[BF_TOTAL];

// ---------------------------------------------------------------------------
__device__ __forceinline__ void split_store(float v, __nv_bfloat16* h, __nv_bfloat16* l) {
    __nv_bfloat16 hi = __float2bfloat16(v);
    *h = hi;
    *l = __float2bfloat16(v - __bfloat162float(hi));
}

// ---------------------------------------------------------------------------
// Mega-prep kernel: weight splits + W_hh prepacks + HF/BAR zero + input T/split
// ---------------------------------------------------------------------------
constexpr size_t WSPLIT_N  = SZ_WINe + SZ_WI0e + SZ_WI1e + SZ_WOe;
constexpr int NB_WSPLIT  = (int)(WSPLIT_N / 256);
constexpr int NB_PREPACK = (int)(SZ_WFp / 256);
constexpr int NB_ZERO    = 514;
constexpr int NB_TRANS   = (Tt / 32) * (INP / 32) * Bb;
constexpr int NB_PREP    = NB_WSPLIT + 2 * NB_PREPACK + NB_ZERO + NB_TRANS;

__device__ __forceinline__ void prepack_one(const float* __restrict__ whh,
                                            unsigned* __restrict__ wfh,
                                            unsigned* __restrict__ wfl, size_t i)
{
    size_t i2 = i;
    int r   = (int)(i2 & 1);  i2 >>= 1;
    int l   = (int)(i2 & 31); i2 >>= 5;
    int ks  = (int)(i2 & 63); i2 >>= 6;
    int t   = (int)(i2 % 6);  i2 /= 6;
    int blk = (int)(i2 & 63); i2 >>= 6;
    int d   = (int)i2;
    int g = t >> 1, half = t & 1;
    int row = g * 1024 + blk * 16 + half * 8 + (l >> 2);
    int k   = ks * 16 + r * 8 + (l & 3) * 2;
    float w0 = whh[((size_t)d * 3072 + row) * 1024 + k];
    float w1 = whh[((size_t)d * 3072 + row) * 1024 + k + 1];
    __nv_bfloat16 h0 = __float2bfloat16(w0);
    __nv_bfloat16 h1 = __float2bfloat16(w1);
    __nv_bfloat16 l0 = __float2bfloat16(w0 - __bfloat162float(h0));
    __nv_bfloat16 l1 = __float2bfloat16(w1 - __bfloat162float(h1));
    wfh[i] = ((unsigned)__bfloat16_as_ushort(h1) << 16) | (unsigned)__bfloat16_as_ushort(h0);
    wfl[i] = ((unsigned)__bfloat16_as_ushort(l1) << 16) | (unsigned)__bfloat16_as_ushort(l0);
}

__global__ void __launch_bounds__(256) prep_kernel(
    const float* __restrict__ inp,
    const float* __restrict__ w_in, const float* __restrict__ w_ih_l0,
    const float* __restrict__ w_ih_l1, const float* __restrict__ w_out,
    const float* __restrict__ whh0, const float* __restrict__ whh1,
    __nv_bfloat16* __restrict__ BF,
    unsigned* __restrict__ WFH0, unsigned* __restrict__ WFL0,
    unsigned* __restrict__ WFH1, unsigned* __restrict__ WFL1,
    unsigned* __restrict__ HF0, unsigned* __restrict__ HF1,
    unsigned* __restrict__ BAR0, unsigned* __restrict__ BAR1)
{
    __shared__ float tile[32][33];
    int bid = blockIdx.x;
    int tid = threadIdx.x;

    if (bid < NB_WSPLIT) {
        size_t i = (size_t)bid * 256 + tid;
        const float* src; size_t hoff, loff, idx;
        if (i < SZ_WINe) {
            src = w_in; idx = i; hoff = BOFF_WINH + i; loff = BOFF_WINL + i;
        } else if (i < SZ_WINe + SZ_WI0e) {
            idx = i - SZ_WINe; src = w_ih_l0; hoff = BOFF_WI0H + idx; loff = BOFF_WI0L + idx;
        } else if (i < SZ_WINe + SZ_WI0e + SZ_WI1e) {
            idx = i - SZ_WINe - SZ_WI0e; src = w_ih_l1; hoff = BOFF_WI1H + idx; loff = BOFF_WI1L + idx;
        } else {
            idx = i - SZ_WINe - SZ_WI0e - SZ_WI1e; src = w_out; hoff = BOFF_WOH + idx; loff = BOFF_WOL + idx;
        }
        split_store(src[idx], BF + hoff, BF + loff);
        return;
    }
    bid -= NB_WSPLIT;

    if (bid < NB_PREPACK) {
        prepack_one(whh0, WFH0, WFL0, (size_t)bid * 256 + tid);
        return;
    }
    bid -= NB_PREPACK;

    if (bid < NB_PREPACK) {
        prepack_one(whh1, WFH1, WFL1, (size_t)bid * 256 + tid);
        return;
    }
    bid -= NB_PREPACK;

    if (bid < NB_ZERO) {
        size_t i = (size_t)bid * 256 + tid;
        if (i < SZ_HF) HF0[i] = 0;
        else if (i < 2 * SZ_HF) HF1[i - SZ_HF] = 0;
        else if (i < 2 * SZ_HF + 64) BAR0[i - 2 * SZ_HF] = 0;
        else if (i < 2 * SZ_HF + 128) BAR1[i - 2 * SZ_HF - 64] = 0;
        return;
    }
    bid -= NB_ZERO;

    // Input transpose + split
    {
        int b   = bid >> 10;
        int rem = bid & 1023;
        int i0  = (rem >> 4) * 32;
        int t0  = (rem & 15) * 32;
        int tx = tid & 31, ty = tid >> 5;
#pragma unroll
        for (int j = 0; j < 32; j += 8)
            tile[ty + j][tx] = inp[((size_t)b * INP + (i0 + ty + j)) * Tt + t0 + tx];
        __syncthreads();
        __nv_bfloat16* XH = BF + BOFF_XH;
        __nv_bfloat16* XL = BF + BOFF_XL;
#pragma unroll
        for (int j = 0; j < 32; j += 8) {
            size_t o = ((size_t)(t0 + ty + j) * Bb + b) * INP + i0 + tx;
            split_store(tile[tx][ty + j], XH + o, XL + o);
        }
    }
}

__global__ void transpose_out_kernel(const float* __restrict__ in, float* __restrict__ out) {
    __shared__ float tile[32][33];
    int b  = blockIdx.z;
    int t0 = blockIdx.x * 32;
    int o0 = blockIdx.y * 32;
    int tx = threadIdx.x, ty = threadIdx.y;
#pragma unroll
    for (int j = 0; j < 32; j += 8)
        tile[ty + j][tx] = in[((size_t)(t0 + ty + j) * Bb + b) * OUTD + o0 + tx];
    __syncthreads();
#pragma unroll
    for (int j = 0; j < 32; j += 8)
        out[((size_t)b * OUTD + (o0 + ty + j)) * Tt + t0 + tx] = tile[tx][ty + j];
}

// ---------------------------------------------------------------------------
// Tensor-core split-bf16 GEMM; 128x128 tile, 2 CTAs/SM (TW=40, 80KB smem).
// Pass-outer mma ordering (dependency distance 16).
// ---------------------------------------------------------------------------
constexpr int TW  = 40;
constexpr int PL  = 128 * TW;
constexpr int GBUF = 4 * PL;
constexpr int SMEM_GEMM = 2 * GBUF * (int)sizeof(__nv_bfloat16);  // 81920

__device__ __forceinline__ void cpa16(void* sdst, const void* gsrc) {
    unsigned s = (unsigned)__cvta_generic_to_shared(sdst);
    asm volatile("cp.async.cg.shared.global [%0], [%1], 16;\n" :: "r"(s), "l"(gsrc));
}
__device__ __forceinline__ void cpa_commit() {
    asm volatile("cp.async.commit_group;\n" ::);
}
__device__ __forceinline__ void cpa_wait0() {
    asm volatile("cp.async.wait_group 0;\n" ::);
}
__device__ __forceinline__ void mma_bf16(float* c, const unsigned* a, const unsigned* b) {
    asm volatile(
        "mma.sync.aligned.m16n8k16.row.col.f32.bf16.bf16.f32 "
        "{%0,%1,%2,%3},{%4,%5,%6,%7},{%8,%9},{%0,%1,%2,%3};\n"
        : "+f"(c[0]), "+f"(c[1]), "+f"(c[2]), "+f"(c[3])
        : "r"(a[0]), "r"(a[1]), "r"(a[2]), "r"(a[3]), "r"(b[0]), "r"(b[1]));
}
__device__ __forceinline__ void ldsm4(unsigned* r, const __nv_bfloat16* p) {
    unsigned a = (unsigned)__cvta_generic_to_shared(p);
    asm volatile("ldmatrix.sync.aligned.m8n8.x4.shared.b16 {%0,%1,%2,%3},[%4];\n"
        : "=r"(r[0]), "=r"(r[1]), "=r"(r[2]), "=r"(r[3]) : "r"(a));
}
__device__ __forceinline__ void ldsm2(unsigned* r, const __nv_bfloat16* p) {
    unsigned a = (unsigned)__cvta_generic_to_shared(p);
    asm volatile("ldmatrix.sync.aligned.m8n8.x2.shared.b16 {%0,%1},[%2];\n"
        : "=r"(r[0]), "=r"(r[1]) : "r"(a));
}

__global__ void __launch_bounds__(256, 2) gemm_bf16_split_kernel(
    const __nv_bfloat16* __restrict__ Ah, const __nv_bfloat16* __restrict__ Al,
    const __nv_bfloat16* __restrict__ Wh, const __nv_bfloat16* __restrict__ Wl,
    const float* __restrict__ bias,
    float* __restrict__ C,
    __nv_bfloat16* __restrict__ CH, __nv_bfloat16* __restrict__ CL,
    int M, int N, int K)
{
    extern __shared__ __nv_bfloat16 smx[];
    const int tid = threadIdx.x;
    const int bm = blockIdx.y * 128, bn = blockIdx.x * 128;
    const int lane = tid & 31, wid = tid >> 5;
    const int wm = wid & 1, wn = wid >> 1;
    const int g = lane >> 2, t = lane & 3;

    float acc[4][4][4];
#pragma unroll
    for (int i = 0; i < 4; ++i)
#pragma unroll
        for (int j = 0; j < 4; ++j)
#pragma unroll
            for (int q = 0; q < 4; ++q) acc[i][j][q] = 0.f;

    const int r0 = tid >> 2;
    const int c0 = (tid & 3) * 8;
    const int nk = K / 32;

    const int aOff = (wm * 64 + (lane & 7) + ((lane >> 3) & 1) * 8) * TW + (lane >> 4) * 8;
    const int lb = lane & 15;
    const int bOff = (wn * 32 + (lb & 7)) * TW + ((lb >> 3) & 1) * 8;

    {
        __nv_bfloat16* s = smx;
#pragma unroll
        for (int p = 0; p < 2; ++p) {
            int row = r0 + p * 64;
            size_t ga = (size_t)(bm + row) * K + c0;
            size_t gw = (size_t)(bn + row) * K + c0;
            int so = row * TW + c0;
            cpa16(s + 0 * PL + so, Ah + ga);
            cpa16(s + 1 * PL + so, Al + ga);
            cpa16(s + 2 * PL + so, Wh + gw);
            cpa16(s + 3 * PL + so, Wl + gw);
        }
        cpa_commit();
    }

    for (int kt = 0; kt < nk; ++kt) {
        cpa_wait0();
        __syncthreads();

        if (kt + 1 < nk) {
            __nv_bfloat16* s = smx + ((kt + 1) & 1) * GBUF;
            int k0 = (kt + 1) * 32;
#pragma unroll
            for (int p = 0; p < 2; ++p) {
                int row = r0 + p * 64;
                size_t ga = (size_t)(bm + row) * K + k0 + c0;
                size_t gw = (size_t)(bn + row) * K + k0 + c0;
                int so = row * TW + c0;
                cpa16(s + 0 * PL + so, Ah + ga);
                cpa16(s + 1 * PL + so, Al + ga);
                cpa16(s + 2 * PL + so, Wh + gw);
                cpa16(s + 3 * PL + so, Wl + gw);
            }
            cpa_commit();
        }

        const __nv_bfloat16* sb = smx + (kt & 1) * GBUF;

#pragma unroll
        for (int ks = 0; ks < 2; ++ks) {
            unsigned aH[4][4], aL[4][4], bH[4][2], bL[4][2];
#pragma unroll
            for (int i = 0; i < 4; ++i) {
                int off = aOff + i * 16 * TW + ks * 16;
                ldsm4(aH[i], sb + 0 * PL + off);
                ldsm4(aL[i], sb + 1 * PL + off);
            }
#pragma unroll
            for (int j = 0; j < 4; ++j) {
                int off = bOff + j * 8 * TW + ks * 16;
                ldsm2(bH[j], sb + 2 * PL + off);
                ldsm2(bL[j], sb + 3 * PL + off);
            }
            // Pass-outer ordering: consecutive mma hit different accumulators
#pragma unroll
            for (int i = 0; i < 4; ++i)
#pragma unroll
                for (int j = 0; j < 4; ++j)
                    mma_bf16(acc[i][j], aH[i], bH[j]);
#pragma unroll
            for (int i = 0; i < 4; ++i)
#pragma unroll
                for (int j = 0; j < 4; ++j)
                    mma_bf16(acc[i][j], aH[i], bL[j]);
#pragma unroll
            for (int i = 0; i < 4; ++i)
#pragma unroll
                for (int j = 0; j < 4; ++j)
                    mma_bf16(acc[i][j], aL[i], bH[j]);
        }
    }

#pragma unroll
    for (int i = 0; i < 4; ++i) {
        int row0 = bm + wm * 64 + i * 16 + g;
#pragma unroll
        for (int j = 0; j < 4; ++j) {
            int col = bn + wn * 32 + j * 8 + t * 2;
            float b0 = bias[col], b1 = bias[col + 1];
            float v00 = acc[i][j][0] + b0, v01 = acc[i][j][1] + b1;
            float v10 = acc[i][j][2] + b0, v11 = acc[i][j][3] + b1;
            if (CH) {
                size_t p0 = (size_t)row0 * N + col;
                size_t p1 = (size_t)(row0 + 8) * N + col;
                __nv_bfloat16 h00 = __float2bfloat16(v00), h01 = __float2bfloat16(v01);
                __nv_bfloat16 h10 = __float2bfloat16(v10), h11 = __float2bfloat16(v11);
                *(__nv_bfloat162*)(CH + p0) = __nv_bfloat162(h00, h01);
                *(__nv_bfloat162*)(CH + p1) = __nv_bfloat162(h10, h11);
                *(__nv_bfloat162*)(CL + p0) = __nv_bfloat162(
                    __float2bfloat16(v00 - __bfloat162float(h00)),
                    __float2bfloat16(v01 - __bfloat162float(h01)));
                *(__nv_bfloat162*)(CL + p1) = __nv_bfloat162(
                    __float2bfloat16(v10 - __bfloat162float(h10)),
                    __float2bfloat16(v11 - __bfloat162float(h11)));
            } else {
                *(float2*)(C + (size_t)row0 * N + col) = make_float2(v00, v01);
                *(float2*)(C + (size_t)(row0 + 8) * N + col) = make_float2(v10, v11);
            }
        }
    }
}

// ---------------------------------------------------------------------------
// Persistent tensor-core bidirectional GRU layer (R7 protocol, MUFU gates,
// pass-outer mma ordering). 256 blocks (128/dir), 8 units/block, 2 CTAs/SM.
// ---------------------------------------------------------------------------
constexpr int WSL_U32 = 3 * 64 * 32 * 2;
constexpr int REC_SMEM = WSL_U32 * 4 + (8 * 3 * 32 * 4) * 4;

__device__ __forceinline__ unsigned ld_acquire(const unsigned* p) {
    unsigned v;
    asm volatile("ld.global.acquire.gpu.u32 %0, [%1];" : "=r"(v) : "l"(p) : "memory");
    return v;
}
__device__ __forceinline__ void red_release_add(unsigned* p, unsigned v) {
    asm volatile("red.release.gpu.global.add.u32 [%0], %1;" :: "l"(p), "r"(v) : "memory");
}
__device__ __forceinline__ float fast_sigmoid(float x) {
    return 1.f / (1.f + __expf(-x));
}
__device__ __forceinline__ float fast_tanh(float x) {
    float e = __expf(2.f * x);
    return (e - 1.f) / (e + 1.f);
}

__global__ void __launch_bounds__(256, 2) gru_layer_tc_kernel(
    const unsigned* __restrict__ WFH, const unsigned* __restrict__ WFL,
    const float* __restrict__ bhh,
    const float* __restrict__ gx,
    __nv_bfloat16* __restrict__ YH, __nv_bfloat16* __restrict__ YL,
    unsigned* __restrict__ HF,
    unsigned* __restrict__ bar)
{
    extern __shared__ unsigned smu[];
    unsigned* wsL = smu;
    float* red = (float*)(smu + WSL_U32);

    const int tid  = threadIdx.x;
    const int dir  = blockIdx.x >> 7;
    const int blk  = blockIdx.x & 127;
    const int B16  = blk >> 1;
    const int half = blk & 1;
    const int u0   = blk * 8;
    const int lane = tid & 31, w = tid >> 5;
    unsigned* bard = bar + dir * 32;

    {
        const unsigned* lbase = WFL + (size_t)(dir * 64 + B16) * (6 * 4096);
#pragma unroll
        for (int t = 0; t < 3; ++t) {
            const uint4* src = (const uint4*)(lbase + (t * 2 + half) * 4096);
            uint4* dst = (uint4*)(wsL + t * 4096);
            for (int i = tid; i < 1024; i += 256) dst[i] = src[i];
        }
    }

    unsigned bHreg[8][3][2];
    {
        const unsigned* hbase = WFH + (size_t)(dir * 64 + B16) * (6 * 4096);
#pragma unroll
        for (int kk = 0; kk < 8; ++kk) {
            int ks = w * 8 + kk;
#pragma unroll
            for (int t = 0; t < 3; ++t) {
                uint2 v = *(const uint2*)(hbase + (t * 2 + half) * 4096 + ks * 64 + lane * 2);
                bHreg[kk][t][0] = v.x;
                bHreg[kk][t][1] = v.y;
            }
        }
    }

    const bool gactive = tid < 128;
    const int gb = tid >> 3;
    const int gu = tid & 7;
    const int gj = u0 + gu;
    float br = 0.f, bz = 0.f, bn2 = 0.f;
    if (gactive) {
        br  = bhh[dir * 3072 + gj];
        bz  = bhh[dir * 3072 + 1024 + gj];
        bn2 = bhh[dir * 3072 + 2048 + gj];
    }
    float hprev = 0.f;

    const int ksb   = blk >> 1;
    const int wlane = ((gb & 7) << 2) + (gu >> 1);
    const int wreg  = (half ? 2 : 0) + ((gb >= 8) ? 1 : 0);
    const int widx  = (ksb * 32 + wlane) * 4 + wreg;
    const int foff  = wlane * 4 + (gu & 1) + ((gb >= 8) ? 2 : 0);

    float xr = 0.f, xz = 0.f, xn = 0.f;
    if (gactive) {
        int tt0 = dir ? (Tt - 1) : 0;
        const float* gxp = gx + (size_t)(tt0 * 16 + gb) * 6144 + dir * 3072;
        xr = __ldg(gxp + gj);
        xz = __ldg(gxp + 1024 + gj);
        xn = __ldg(gxp + 2048 + gj);
    }

    __syncthreads();

    for (int s = 0; s < Tt; ++s) {
        const int cur = s & 1, nxt = cur ^ 1;
        const int tt  = dir ? (Tt - 1 - s) : s;

        float acc[3][4];
#pragma unroll
        for (int t = 0; t < 3; ++t)
#pragma unroll
            for (int q = 0; q < 4; ++q) acc[t][q] = 0.f;

        const unsigned* hfH = HF + ((size_t)(cur * 2 + dir) * 2 + 0) * 8192;
        const unsigned* hfL = HF + ((size_t)(cur * 2 + dir) * 2 + 1) * 8192;

#pragma unroll
        for (int kk = 0; kk < 8; ++kk) {
            int ks = w * 8 + kk;
            uint4 AHv = __ldcg((const uint4*)(hfH + (ks * 32 + lane) * 4));
            uint4 ALv = __ldcg((const uint4*)(hfL + (ks * 32 + lane) * 4));
            unsigned aH[4] = {AHv.x, AHv.y, AHv.z, AHv.w};
            unsigned aL[4] = {ALv.x, ALv.y, ALv.z, ALv.w};
            // Pass-outer ordering: consecutive mma hit different acc[t]
#pragma unroll
            for (int t = 0; t < 3; ++t)
                mma_bf16(acc[t], aH, bHreg[kk][t]);
#pragma unroll
            for (int t = 0; t < 3; ++t)
                mma_bf16(acc[t], aL, bHreg[kk][t]);
#pragma unroll
            for (int t = 0; t < 3; ++t) {
                uint2 bLv = *(const uint2*)&wsL[t * 4096 + ks * 64 + lane * 2];
                unsigned bL[2] = {bLv.x, bLv.y};
                mma_bf16(acc[t], aH, bL);
            }
        }
#pragma unroll
        for (int t = 0; t < 3; ++t)
            *(float4*)&red[((w * 3 + t) * 32 + lane) * 4] =
                make_float4(acc[t][0], acc[t][1], acc[t][2], acc[t][3]);
        __syncthreads();

        if (gactive) {
            float ghr = br, ghz = bz, ghn = bn2;
#pragma unroll
            for (int ww = 0; ww < 8; ++ww) {
                ghr += red[(ww * 3 + 0) * 128 + foff];
                ghz += red[(ww * 3 + 1) * 128 + foff];
                ghn += red[(ww * 3 + 2) * 128 + foff];
            }
            float r = fast_sigmoid(xr + ghr);
            float z = fast_sigmoid(xz + ghz);
            float n = fast_tanh(xn + r * ghn);
            float hnew = (1.f - z) * n + z * hprev;
            hprev = hnew;

            __nv_bfloat16 hhi = __float2bfloat16(hnew);
            float rlo = hnew - __bfloat162float(hhi);
            __nv_bfloat16 hlo = __float2bfloat16(rlo);
            unsigned vh = (unsigned)__bfloat16_as_ushort(hhi);
            unsigned vl = (unsigned)__bfloat16_as_ushort(hlo);
            unsigned phh = __shfl_down_sync(0xffffffffu, vh, 1);
            unsigned pll = __shfl_down_sync(0xffffffffu, vl, 1);
            if ((gu & 1) == 0) {
                unsigned hp = (phh << 16) | vh;
                unsigned lp = (pll << 16) | vl;
                unsigned* oH = HF + ((size_t)(nxt * 2 + dir) * 2 + 0) * 8192;
                unsigned* oL = HF + ((size_t)(nxt * 2 + dir) * 2 + 1) * 8192;
                oH[widx] = hp;
                oL[widx] = lp;
                size_t yi = (size_t)(tt * 16 + gb) * 1024 + dir * 512 + (gj >> 1);
                ((unsigned*)YH)[yi] = hp;
                ((unsigned*)YL)[yi] = lp;
            }

            if (s + 1 < Tt) {
                int ttn = dir ? (Tt - 2 - s) : (s + 1);
                const float* gxn = gx + (size_t)(ttn * 16 + gb) * 6144 + dir * 3072;
                xr = __ldg(gxn + gj);
                xz = __ldg(gxn + 1024 + gj);
                xn = __ldg(gxn + 2048 + gj);
            }
        }

        __syncthreads();
        if (tid == 0) {
            red_release_add(bard, 1u);
            unsigned tgt = (unsigned)(s + 1) * 128;
            while (ld_acquire(bard) < tgt) { }
        }
        __syncthreads();
    }
}

// ---------------------------------------------------------------------------
extern "C" void kernel_launch(void* const* d_in, const int* in_sizes, int n_in,
                              void* d_out, int out_size)
{
    const float* inp     = (const float*)d_in[0];
    const float* w_in    = (const float*)d_in[1];
    const float* b_in    = (const float*)d_in[2];
    const float* w_ih_l0 = (const float*)d_in[3];
    const float* w_hh_l0 = (const float*)d_in[4];
    const float* b_ih_l0 = (const float*)d_in[5];
    const float* b_hh_l0 = (const float*)d_in[6];
    const float* w_ih_l1 = (const float*)d_in[7];
    const float* w_hh_l1 = (const float*)d_in[8];
    const float* b_ih_l1 = (const float*)d_in[9];
    const float* b_hh_l1 = (const float*)d_in[10];
    const float* w_out   = (const float*)d_in[11];
    const float* b_out   = (const float*)d_in[12];
    float* out = (float*)d_out;

    float* S = nullptr;
    cudaGetSymbolAddress((void**)&S, g_scratch);
    __nv_bfloat16* BF = nullptr;
    cudaGetSymbolAddress((void**)&BF, g_bf);

    float* GX0  = S + OFF_GX0;
    float* GX1  = S + OFF_GX1;
    float* OUTT = S + OFF_OUTT;
    unsigned* WFH0 = (unsigned*)(S + OFF_WFH0);
    unsigned* WFL0 = (unsigned*)(S + OFF_WFL0);
    unsigned* WFH1 = (unsigned*)(S + OFF_WFH1);
    unsigned* WFL1 = (unsigned*)(S + OFF_WFL1);
    unsigned* HF0  = (unsigned*)(S + OFF_HF0);
    unsigned* HF1  = (unsigned*)(S + OFF_HF1);
    unsigned* BAR0 = (unsigned*)(S + OFF_BAR0);
    unsigned* BAR1 = (unsigned*)(S + OFF_BAR1);

    cudaFuncSetAttribute(gemm_bf16_split_kernel,
                         cudaFuncAttributeMaxDynamicSharedMemorySize, SMEM_GEMM);
    cudaFuncSetAttribute(gru_layer_tc_kernel,
                         cudaFuncAttributeMaxDynamicSharedMemorySize, REC_SMEM);

    const int M = Tt * Bb;  // 8192

    // 1) Mega-prep
    prep_kernel<<<NB_PREP, 256>>>(inp, w_in, w_ih_l0, w_ih_l1, w_out,
                                  w_hh_l0, w_hh_l1, BF,
                                  WFH0, WFL0, WFH1, WFL1, HF0, HF1, BAR0, BAR1);

    // 2) Input projection (bf16 split output)
    gemm_bf16_split_kernel<<<dim3(F / 128, M / 128), 256, SMEM_GEMM>>>(
        BF + BOFF_XH, BF + BOFF_XL, BF + BOFF_WINH, BF + BOFF_WINL, b_in,
        nullptr, BF + BOFF_H0H, BF + BOFF_H0L, M, F, INP);

    // 3) Layer 0 gx
    gemm_bf16_split_kernel<<<dim3(6 * F / 128, M / 128), 256, SMEM_GEMM>>>(
        BF + BOFF_H0H, BF + BOFF_H0L, BF + BOFF_WI0H, BF + BOFF_WI0L, b_ih_l0,
        GX0, nullptr, nullptr, M, 6 * F, F);

    // 4) Layer 0 recurrence  <-- ncu capture slot
    gru_layer_tc_kernel<<<256, 256, REC_SMEM>>>(
        WFH0, WFL0, b_hh_l0, GX0, BF + BOFF_Y0H, BF + BOFF_Y0L, HF0, BAR0);

    // 5) Layer 1 gx
    gemm_bf16_split_kernel<<<dim3(6 * F / 128, M / 128), 256, SMEM_GEMM>>>(
        BF + BOFF_Y0H, BF + BOFF_Y0L, BF + BOFF_WI1H, BF + BOFF_WI1L, b_ih_l1,
        GX1, nullptr, nullptr, M, 6 * F, 2 * F);

    // 6) Layer 1 recurrence
    gru_layer_tc_kernel<<<256, 256, REC_SMEM>>>(
        WFH1, WFL1, b_hh_l1, GX1, BF + BOFF_Y1H, BF + BOFF_Y1L, HF1, BAR1);

    // 7) Output projection
    gemm_bf16_split_kernel<<<dim3(OUTD / 128, M / 128), 256, SMEM_GEMM>>>(
        BF + BOFF_Y1H, BF + BOFF_Y1L, BF + BOFF_WOH, BF + BOFF_WOL, b_out,
        OUTT, nullptr, nullptr, M, OUTD, 2 * F);

    // 8) Final transpose
    transpose_out_kernel<<<dim3(Tt / 32, OUTD / 32, Bb), dim3(32, 8)>>>(OUTT, out);
}

// round 15
// speedup vs baseline: 1.0482x; 1.0049x over previous
#include <cuda_runtime.h>
#include <cuda_bf16.h>
#include <cstddef>

// Problem constants
constexpr int Tt   = 512;
constexpr int Bb   = 16;
constexpr int F    = 1024;
constexpr int INP  = 2048;
constexpr int OUTD = 1024;

// ---------------------------------------------------------------------------
// Float/u32 scratch
// ---------------------------------------------------------------------------
constexpr size_t OFF_GX0  = 0;
constexpr size_t SZ_GX    = (size_t)Tt * Bb * 6 * F;
constexpr size_t OFF_GX1  = OFF_GX0 + SZ_GX;
constexpr size_t OFF_OUTT = OFF_GX1 + SZ_GX;
constexpr size_t SZ_OUTT  = (size_t)Tt * Bb * OUTD;
constexpr size_t SZ_WFp   = (size_t)2 * 64 * 6 * 64 * 32 * 2;   // 3145728
constexpr size_t OFF_WFH0 = OFF_OUTT + SZ_OUTT;
constexpr size_t OFF_WFL0 = OFF_WFH0 + SZ_WFp;
constexpr size_t OFF_WFH1 = OFF_WFL0 + SZ_WFp;
constexpr size_t OFF_WFL1 = OFF_WFH1 + SZ_WFp;
constexpr size_t SZ_HF    = (size_t)2 * 2 * 2 * 64 * 32 * 4;    // 65536
constexpr size_t OFF_HF0  = OFF_WFL1 + SZ_WFp;
constexpr size_t OFF_HF1  = OFF_HF0 + SZ_HF;
constexpr size_t OFF_BAR0 = OFF_HF1 + SZ_HF;    // 64 u32 (2 dirs, 128B apart)
constexpr size_t OFF_BAR1 = OFF_BAR0 + 64;
constexpr size_t SCRATCH_TOTAL = OFF_BAR1 + 64;

__device__ float g_scratch[SCRATCH_TOTAL];

// ---------------------------------------------------------------------------
// bf16 scratch (hi/lo planes)
// ---------------------------------------------------------------------------
constexpr size_t SZ_Xe   = (size_t)Tt * Bb * INP;
constexpr size_t SZ_H0e  = (size_t)Tt * Bb * F;
constexpr size_t SZ_Ye   = (size_t)Tt * Bb * 2 * F;
constexpr size_t SZ_WINe = (size_t)F * INP;
constexpr size_t SZ_WI0e = (size_t)6 * F * F;
constexpr size_t SZ_WI1e = (size_t)6 * F * 2 * F;
constexpr size_t SZ_WOe  = (size_t)OUTD * 2 * F;

constexpr size_t BOFF_XH  = 0;
constexpr size_t BOFF_XL  = BOFF_XH  + SZ_Xe;
constexpr size_t BOFF_H0H = BOFF_XL  + SZ_Xe;
constexpr size_t BOFF_H0L = BOFF_H0H + SZ_H0e;
constexpr size_t BOFF_Y0H = BOFF_H0L + SZ_H0e;
constexpr size_t BOFF_Y0L = BOFF_Y0H + SZ_Ye;
constexpr size_t BOFF_Y1H = BOFF_Y0L + SZ_Ye;
constexpr size_t BOFF_Y1L = BOFF_Y1H + SZ_Ye;
constexpr size_t BOFF_WINH= BOFF_Y1L + SZ_Ye;
constexpr size_t BOFF_WINL= BOFF_WINH+ SZ_WINe;
constexpr size_t BOFF_WI0H= BOFF_WINL+ SZ_WINe;
constexpr size_t BOFF_WI0L= BOFF_WI0H+ SZ_WI0e;
constexpr size_t BOFF_WI1H= BOFF_WI0L+ SZ_WI0e;
constexpr size_t BOFF_WI1L= BOFF_WI1H+ SZ_WI1e;
constexpr size_t BOFF_WOH = BOFF_WI1L+ SZ_WI1e;
constexpr size_t BOFF_WOL = BOFF_WOH + SZ_WOe;
constexpr size_t BF_TOTAL = BOFF_WOL + SZ_WOe;

__device__ __nv_bfloat16 g_bf[BF_TOTAL];

// ---------------------------------------------------------------------------
__device__ __forceinline__ void split_store(float v, __nv_bfloat16* h, __nv_bfloat16* l) {
    __nv_bfloat16 hi = __float2bfloat16(v);
    *h = hi;
    *l = __float2bfloat16(v - __bfloat162float(hi));
}

// ---------------------------------------------------------------------------
// Mega-prep kernel: weight splits + W_hh prepacks + HF/BAR zero + input T/split
// ---------------------------------------------------------------------------
constexpr size_t WSPLIT_N  = SZ_WINe + SZ_WI0e + SZ_WI1e + SZ_WOe;
constexpr int NB_WSPLIT  = (int)(WSPLIT_N / 256);
constexpr int NB_PREPACK = (int)(SZ_WFp / 256);
constexpr int NB_ZERO    = 514;
constexpr int NB_TRANS   = (Tt / 32) * (INP / 32) * Bb;
constexpr int NB_PREP    = NB_WSPLIT + 2 * NB_PREPACK + NB_ZERO + NB_TRANS;

__device__ __forceinline__ void prepack_one(const float* __restrict__ whh,
                                            unsigned* __restrict__ wfh,
                                            unsigned* __restrict__ wfl, size_t i)
{
    size_t i2 = i;
    int r   = (int)(i2 & 1);  i2 >>= 1;
    int l   = (int)(i2 & 31); i2 >>= 5;
    int ks  = (int)(i2 & 63); i2 >>= 6;
    int t   = (int)(i2 % 6);  i2 /= 6;
    int blk = (int)(i2 & 63); i2 >>= 6;
    int d   = (int)i2;
    int g = t >> 1, half = t & 1;
    int row = g * 1024 + blk * 16 + half * 8 + (l >> 2);
    int k   = ks * 16 + r * 8 + (l & 3) * 2;
    float w0 = whh[((size_t)d * 3072 + row) * 1024 + k];
    float w1 = whh[((size_t)d * 3072 + row) * 1024 + k + 1];
    __nv_bfloat16 h0 = __float2bfloat16(w0);
    __nv_bfloat16 h1 = __float2bfloat16(w1);
    __nv_bfloat16 l0 = __float2bfloat16(w0 - __bfloat162float(h0));
    __nv_bfloat16 l1 = __float2bfloat16(w1 - __bfloat162float(h1));
    wfh[i] = ((unsigned)__bfloat16_as_ushort(h1) << 16) | (unsigned)__bfloat16_as_ushort(h0);
    wfl[i] = ((unsigned)__bfloat16_as_ushort(l1) << 16) | (unsigned)__bfloat16_as_ushort(l0);
}

__global__ void __launch_bounds__(256) prep_kernel(
    const float* __restrict__ inp,
    const float* __restrict__ w_in, const float* __restrict__ w_ih_l0,
    const float* __restrict__ w_ih_l1, const float* __restrict__ w_out,
    const float* __restrict__ whh0, const float* __restrict__ whh1,
    __nv_bfloat16* __restrict__ BF,
    unsigned* __restrict__ WFH0, unsigned* __restrict__ WFL0,
    unsigned* __restrict__ WFH1, unsigned* __restrict__ WFL1,
    unsigned* __restrict__ HF0, unsigned* __restrict__ HF1,
    unsigned* __restrict__ BAR0, unsigned* __restrict__ BAR1)
{
    __shared__ float tile[32][33];
    int bid = blockIdx.x;
    int tid = threadIdx.x;

    if (bid < NB_WSPLIT) {
        size_t i = (size_t)bid * 256 + tid;
        const float* src; size_t hoff, loff, idx;
        if (i < SZ_WINe) {
            src = w_in; idx = i; hoff = BOFF_WINH + i; loff = BOFF_WINL + i;
        } else if (i < SZ_WINe + SZ_WI0e) {
            idx = i - SZ_WINe; src = w_ih_l0; hoff = BOFF_WI0H + idx; loff = BOFF_WI0L + idx;
        } else if (i < SZ_WINe + SZ_WI0e + SZ_WI1e) {
            idx = i - SZ_WINe - SZ_WI0e; src = w_ih_l1; hoff = BOFF_WI1H + idx; loff = BOFF_WI1L + idx;
        } else {
            idx = i - SZ_WINe - SZ_WI0e - SZ_WI1e; src = w_out; hoff = BOFF_WOH + idx; loff = BOFF_WOL + idx;
        }
        split_store(src[idx], BF + hoff, BF + loff);
        return;
    }
    bid -= NB_WSPLIT;

    if (bid < NB_PREPACK) {
        prepack_one(whh0, WFH0, WFL0, (size_t)bid * 256 + tid);
        return;
    }
    bid -= NB_PREPACK;

    if (bid < NB_PREPACK) {
        prepack_one(whh1, WFH1, WFL1, (size_t)bid * 256 + tid);
        return;
    }
    bid -= NB_PREPACK;

    if (bid < NB_ZERO) {
        size_t i = (size_t)bid * 256 + tid;
        if (i < SZ_HF) HF0[i] = 0;
        else if (i < 2 * SZ_HF) HF1[i - SZ_HF] = 0;
        else if (i < 2 * SZ_HF + 64) BAR0[i - 2 * SZ_HF] = 0;
        else if (i < 2 * SZ_HF + 128) BAR1[i - 2 * SZ_HF - 64] = 0;
        return;
    }
    bid -= NB_ZERO;

    // Input transpose + split
    {
        int b   = bid >> 10;
        int rem = bid & 1023;
        int i0  = (rem >> 4) * 32;
        int t0  = (rem & 15) * 32;
        int tx = tid & 31, ty = tid >> 5;
#pragma unroll
        for (int j = 0; j < 32; j += 8)
            tile[ty + j][tx] = inp[((size_t)b * INP + (i0 + ty + j)) * Tt + t0 + tx];
        __syncthreads();
        __nv_bfloat16* XH = BF + BOFF_XH;
        __nv_bfloat16* XL = BF + BOFF_XL;
#pragma unroll
        for (int j = 0; j < 32; j += 8) {
            size_t o = ((size_t)(t0 + ty + j) * Bb + b) * INP + i0 + tx;
            split_store(tile[tx][ty + j], XH + o, XL + o);
        }
    }
}

__global__ void transpose_out_kernel(const float* __restrict__ in, float* __restrict__ out) {
    __shared__ float tile[32][33];
    int b  = blockIdx.z;
    int t0 = blockIdx.x * 32;
    int o0 = blockIdx.y * 32;
    int tx = threadIdx.x, ty = threadIdx.y;
#pragma unroll
    for (int j = 0; j < 32; j += 8)
        tile[ty + j][tx] = in[((size_t)(t0 + ty + j) * Bb + b) * OUTD + o0 + tx];
    __syncthreads();
#pragma unroll
    for (int j = 0; j < 32; j += 8)
        out[((size_t)b * OUTD + (o0 + ty + j)) * Tt + t0 + tx] = tile[tx][ty + j];
}

// ---------------------------------------------------------------------------
// Tensor-core split-bf16 GEMM; 128x128 tile, 2 CTAs/SM (TW=40, 80KB smem).
// A planes staged via cp.async.ca (L1-shared between co-resident CTAs that
// share the same bm); W planes via cp.async.cg. Pass-outer mma ordering.
// ---------------------------------------------------------------------------
constexpr int TW  = 40;
constexpr int PL  = 128 * TW;
constexpr int GBUF = 4 * PL;
constexpr int SMEM_GEMM = 2 * GBUF * (int)sizeof(__nv_bfloat16);  // 81920

__device__ __forceinline__ void cpa16_cg(void* sdst, const void* gsrc) {
    unsigned s = (unsigned)__cvta_generic_to_shared(sdst);
    asm volatile("cp.async.cg.shared.global [%0], [%1], 16;\n" :: "r"(s), "l"(gsrc));
}
__device__ __forceinline__ void cpa16_ca(void* sdst, const void* gsrc) {
    unsigned s = (unsigned)__cvta_generic_to_shared(sdst);
    asm volatile("cp.async.ca.shared.global [%0], [%1], 16;\n" :: "r"(s), "l"(gsrc));
}
__device__ __forceinline__ void cpa_commit() {
    asm volatile("cp.async.commit_group;\n" ::);
}
__device__ __forceinline__ void cpa_wait0() {
    asm volatile("cp.async.wait_group 0;\n" ::);
}
__device__ __forceinline__ void mma_bf16(float* c, const unsigned* a, const unsigned* b) {
    asm volatile(
        "mma.sync.aligned.m16n8k16.row.col.f32.bf16.bf16.f32 "
        "{%0,%1,%2,%3},{%4,%5,%6,%7},{%8,%9},{%0,%1,%2,%3};\n"
        : "+f"(c[0]), "+f"(c[1]), "+f"(c[2]), "+f"(c[3])
        : "r"(a[0]), "r"(a[1]), "r"(a[2]), "r"(a[3]), "r"(b[0]), "r"(b[1]));
}
__device__ __forceinline__ void ldsm4(unsigned* r, const __nv_bfloat16* p) {
    unsigned a = (unsigned)__cvta_generic_to_shared(p);
    asm volatile("ldmatrix.sync.aligned.m8n8.x4.shared.b16 {%0,%1,%2,%3},[%4];\n"
        : "=r"(r[0]), "=r"(r[1]), "=r"(r[2]), "=r"(r[3]) : "r"(a));
}
__device__ __forceinline__ void ldsm2(unsigned* r, const __nv_bfloat16* p) {
    unsigned a = (unsigned)__cvta_generic_to_shared(p);
    asm volatile("ldmatrix.sync.aligned.m8n8.x2.shared.b16 {%0,%1},[%2];\n"
        : "=r"(r[0]), "=r"(r[1]) : "r"(a));
}

__global__ void __launch_bounds__(256, 2) gemm_bf16_split_kernel(
    const __nv_bfloat16* __restrict__ Ah, const __nv_bfloat16* __restrict__ Al,
    const __nv_bfloat16* __restrict__ Wh, const __nv_bfloat16* __restrict__ Wl,
    const float* __restrict__ bias,
    float* __restrict__ C,
    __nv_bfloat16* __restrict__ CH, __nv_bfloat16* __restrict__ CL,
    int M, int N, int K)
{
    extern __shared__ __nv_bfloat16 smx[];
    const int tid = threadIdx.x;
    const int bm = blockIdx.y * 128, bn = blockIdx.x * 128;
    const int lane = tid & 31, wid = tid >> 5;
    const int wm = wid & 1, wn = wid >> 1;
    const int g = lane >> 2, t = lane & 3;

    float acc[4][4][4];
#pragma unroll
    for (int i = 0; i < 4; ++i)
#pragma unroll
        for (int j = 0; j < 4; ++j)
#pragma unroll
            for (int q = 0; q < 4; ++q) acc[i][j][q] = 0.f;

    const int r0 = tid >> 2;
    const int c0 = (tid & 3) * 8;
    const int nk = K / 32;

    const int aOff = (wm * 64 + (lane & 7) + ((lane >> 3) & 1) * 8) * TW + (lane >> 4) * 8;
    const int lb = lane & 15;
    const int bOff = (wn * 32 + (lb & 7)) * TW + ((lb >> 3) & 1) * 8;

    {
        __nv_bfloat16* s = smx;
#pragma unroll
        for (int p = 0; p < 2; ++p) {
            int row = r0 + p * 64;
            size_t ga = (size_t)(bm + row) * K + c0;
            size_t gw = (size_t)(bn + row) * K + c0;
            int so = row * TW + c0;
            cpa16_ca(s + 0 * PL + so, Ah + ga);
            cpa16_ca(s + 1 * PL + so, Al + ga);
            cpa16_cg(s + 2 * PL + so, Wh + gw);
            cpa16_cg(s + 3 * PL + so, Wl + gw);
        }
        cpa_commit();
    }

    for (int kt = 0; kt < nk; ++kt) {
        cpa_wait0();
        __syncthreads();

        if (kt + 1 < nk) {
            __nv_bfloat16* s = smx + ((kt + 1) & 1) * GBUF;
            int k0 = (kt + 1) * 32;
#pragma unroll
            for (int p = 0; p < 2; ++p) {
                int row = r0 + p * 64;
                size_t ga = (size_t)(bm + row) * K + k0 + c0;
                size_t gw = (size_t)(bn + row) * K + k0 + c0;
                int so = row * TW + c0;
                cpa16_ca(s + 0 * PL + so, Ah + ga);
                cpa16_ca(s + 1 * PL + so, Al + ga);
                cpa16_cg(s + 2 * PL + so, Wh + gw);
                cpa16_cg(s + 3 * PL + so, Wl + gw);
            }
            cpa_commit();
        }

        const __nv_bfloat16* sb = smx + (kt & 1) * GBUF;

#pragma unroll
        for (int ks = 0; ks < 2; ++ks) {
            unsigned aH[4][4], aL[4][4], bH[4][2], bL[4][2];
#pragma unroll
            for (int i = 0; i < 4; ++i) {
                int off = aOff + i * 16 * TW + ks * 16;
                ldsm4(aH[i], sb + 0 * PL + off);
                ldsm4(aL[i], sb + 1 * PL + off);
            }
#pragma unroll
            for (int j = 0; j < 4; ++j) {
                int off = bOff + j * 8 * TW + ks * 16;
                ldsm2(bH[j], sb + 2 * PL + off);
                ldsm2(bL[j], sb + 3 * PL + off);
            }
            // Pass-outer ordering: consecutive mma hit different accumulators
#pragma unroll
            for (int i = 0; i < 4; ++i)
#pragma unroll
                for (int j = 0; j < 4; ++j)
                    mma_bf16(acc[i][j], aH[i], bH[j]);
#pragma unroll
            for (int i = 0; i < 4; ++i)
#pragma unroll
                for (int j = 0; j < 4; ++j)
                    mma_bf16(acc[i][j], aH[i], bL[j]);
#pragma unroll
            for (int i = 0; i < 4; ++i)
#pragma unroll
                for (int j = 0; j < 4; ++j)
                    mma_bf16(acc[i][j], aL[i], bH[j]);
        }
    }

#pragma unroll
    for (int i = 0; i < 4; ++i) {
        int row0 = bm + wm * 64 + i * 16 + g;
#pragma unroll
        for (int j = 0; j < 4; ++j) {
            int col = bn + wn * 32 + j * 8 + t * 2;
            float b0 = bias[col], b1 = bias[col + 1];
            float v00 = acc[i][j][0] + b0, v01 = acc[i][j][1] + b1;
            float v10 = acc[i][j][2] + b0, v11 = acc[i][j][3] + b1;
            if (CH) {
                size_t p0 = (size_t)row0 * N + col;
                size_t p1 = (size_t)(row0 + 8) * N + col;
                __nv_bfloat16 h00 = __float2bfloat16(v00), h01 = __float2bfloat16(v01);
                __nv_bfloat16 h10 = __float2bfloat16(v10), h11 = __float2bfloat16(v11);
                *(__nv_bfloat162*)(CH + p0) = __nv_bfloat162(h00, h01);
                *(__nv_bfloat162*)(CH + p1) = __nv_bfloat162(h10, h11);
                *(__nv_bfloat162*)(CL + p0) = __nv_bfloat162(
                    __float2bfloat16(v00 - __bfloat162float(h00)),
                    __float2bfloat16(v01 - __bfloat162float(h01)));
                *(__nv_bfloat162*)(CL + p1) = __nv_bfloat162(
                    __float2bfloat16(v10 - __bfloat162float(h10)),
                    __float2bfloat16(v11 - __bfloat162float(h11)));
            } else {
                *(float2*)(C + (size_t)row0 * N + col) = make_float2(v00, v01);
                *(float2*)(C + (size_t)(row0 + 8) * N + col) = make_float2(v10, v11);
            }
        }
    }
}

// ---------------------------------------------------------------------------
// Persistent tensor-core bidirectional GRU layer (R7 protocol, MUFU gates,
// pass-outer mma ordering). 256 blocks (128/dir), 8 units/block, 2 CTAs/SM.
// ---------------------------------------------------------------------------
constexpr int WSL_U32 = 3 * 64 * 32 * 2;
constexpr int REC_SMEM = WSL_U32 * 4 + (8 * 3 * 32 * 4) * 4;

__device__ __forceinline__ unsigned ld_acquire(const unsigned* p) {
    unsigned v;
    asm volatile("ld.global.acquire.gpu.u32 %0, [%1];" : "=r"(v) : "l"(p) : "memory");
    return v;
}
__device__ __forceinline__ void red_release_add(unsigned* p, unsigned v) {
    asm volatile("red.release.gpu.global.add.u32 [%0], %1;" :: "l"(p), "r"(v) : "memory");
}
__device__ __forceinline__ float fast_sigmoid(float x) {
    return 1.f / (1.f + __expf(-x));
}
__device__ __forceinline__ float fast_tanh(float x) {
    float e = __expf(2.f * x);
    return (e - 1.f) / (e + 1.f);
}

__global__ void __launch_bounds__(256, 2) gru_layer_tc_kernel(
    const unsigned* __restrict__ WFH, const unsigned* __restrict__ WFL,
    const float* __restrict__ bhh,
    const float* __restrict__ gx,
    __nv_bfloat16* __restrict__ YH, __nv_bfloat16* __restrict__ YL,
    unsigned* __restrict__ HF,
    unsigned* __restrict__ bar)
{
    extern __shared__ unsigned smu[];
    unsigned* wsL = smu;
    float* red = (float*)(smu + WSL_U32);

    const int tid  = threadIdx.x;
    const int dir  = blockIdx.x >> 7;
    const int blk  = blockIdx.x & 127;
    const int B16  = blk >> 1;
    const int half = blk & 1;
    const int u0   = blk * 8;
    const int lane = tid & 31, w = tid >> 5;
    unsigned* bard = bar + dir * 32;

    {
        const unsigned* lbase = WFL + (size_t)(dir * 64 + B16) * (6 * 4096);
#pragma unroll
        for (int t = 0; t < 3; ++t) {
            const uint4* src = (const uint4*)(lbase + (t * 2 + half) * 4096);
            uint4* dst = (uint4*)(wsL + t * 4096);
            for (int i = tid; i < 1024; i += 256) dst[i] = src[i];
        }
    }

    unsigned bHreg[8][3][2];
    {
        const unsigned* hbase = WFH + (size_t)(dir * 64 + B16) * (6 * 4096);
#pragma unroll
        for (int kk = 0; kk < 8; ++kk) {
            int ks = w * 8 + kk;
#pragma unroll
            for (int t = 0; t < 3; ++t) {
                uint2 v = *(const uint2*)(hbase + (t * 2 + half) * 4096 + ks * 64 + lane * 2);
                bHreg[kk][t][0] = v.x;
                bHreg[kk][t][1] = v.y;
            }
        }
    }

    const bool gactive = tid < 128;
    const int gb = tid >> 3;
    const int gu = tid & 7;
    const int gj = u0 + gu;
    float br = 0.f, bz = 0.f, bn2 = 0.f;
    if (gactive) {
        br  = bhh[dir * 3072 + gj];
        bz  = bhh[dir * 3072 + 1024 + gj];
        bn2 = bhh[dir * 3072 + 2048 + gj];
    }
    float hprev = 0.f;

    const int ksb   = blk >> 1;
    const int wlane = ((gb & 7) << 2) + (gu >> 1);
    const int wreg  = (half ? 2 : 0) + ((gb >= 8) ? 1 : 0);
    const int widx  = (ksb * 32 + wlane) * 4 + wreg;
    const int foff  = wlane * 4 + (gu & 1) + ((gb >= 8) ? 2 : 0);

    float xr = 0.f, xz = 0.f, xn = 0.f;
    if (gactive) {
        int tt0 = dir ? (Tt - 1) : 0;
        const float* gxp = gx + (size_t)(tt0 * 16 + gb) * 6144 + dir * 3072;
        xr = __ldg(gxp + gj);
        xz = __ldg(gxp + 1024 + gj);
        xn = __ldg(gxp + 2048 + gj);
    }

    __syncthreads();

    for (int s = 0; s < Tt; ++s) {
        const int cur = s & 1, nxt = cur ^ 1;
        const int tt  = dir ? (Tt - 1 - s) : s;

        float acc[3][4];
#pragma unroll
        for (int t = 0; t < 3; ++t)
#pragma unroll
            for (int q = 0; q < 4; ++q) acc[t][q] = 0.f;

        const unsigned* hfH = HF + ((size_t)(cur * 2 + dir) * 2 + 0) * 8192;
        const unsigned* hfL = HF + ((size_t)(cur * 2 + dir) * 2 + 1) * 8192;

#pragma unroll
        for (int kk = 0; kk < 8; ++kk) {
            int ks = w * 8 + kk;
            uint4 AHv = __ldcg((const uint4*)(hfH + (ks * 32 + lane) * 4));
            uint4 ALv = __ldcg((const uint4*)(hfL + (ks * 32 + lane) * 4));
            unsigned aH[4] = {AHv.x, AHv.y, AHv.z, AHv.w};
            unsigned aL[4] = {ALv.x, ALv.y, ALv.z, ALv.w};
            // Pass-outer ordering: consecutive mma hit different acc[t]
#pragma unroll
            for (int t = 0; t < 3; ++t)
                mma_bf16(acc[t], aH, bHreg[kk][t]);
#pragma unroll
            for (int t = 0; t < 3; ++t)
                mma_bf16(acc[t], aL, bHreg[kk][t]);
#pragma unroll
            for (int t = 0; t < 3; ++t) {
                uint2 bLv = *(const uint2*)&wsL[t * 4096 + ks * 64 + lane * 2];
                unsigned bL[2] = {bLv.x, bLv.y};
                mma_bf16(acc[t], aH, bL);
            }
        }
#pragma unroll
        for (int t = 0; t < 3; ++t)
            *(float4*)&red[((w * 3 + t) * 32 + lane) * 4] =
                make_float4(acc[t][0], acc[t][1], acc[t][2], acc[t][3]);
        __syncthreads();

        if (gactive) {
            float ghr = br, ghz = bz, ghn = bn2;
#pragma unroll
            for (int ww = 0; ww < 8; ++ww) {
                ghr += red[(ww * 3 + 0) * 128 + foff];
                ghz += red[(ww * 3 + 1) * 128 + foff];
                ghn += red[(ww * 3 + 2) * 128 + foff];
            }
            float r = fast_sigmoid(xr + ghr);
            float z = fast_sigmoid(xz + ghz);
            float n = fast_tanh(xn + r * ghn);
            float hnew = (1.f - z) * n + z * hprev;
            hprev = hnew;

            __nv_bfloat16 hhi = __float2bfloat16(hnew);
            float rlo = hnew - __bfloat162float(hhi);
            __nv_bfloat16 hlo = __float2bfloat16(rlo);
            unsigned vh = (unsigned)__bfloat16_as_ushort(hhi);
            unsigned vl = (unsigned)__bfloat16_as_ushort(hlo);
            unsigned phh = __shfl_down_sync(0xffffffffu, vh, 1);
            unsigned pll = __shfl_down_sync(0xffffffffu, vl, 1);
            if ((gu & 1) == 0) {
                unsigned hp = (phh << 16) | vh;
                unsigned lp = (pll << 16) | vl;
                unsigned* oH = HF + ((size_t)(nxt * 2 + dir) * 2 + 0) * 8192;
                unsigned* oL = HF + ((size_t)(nxt * 2 + dir) * 2 + 1) * 8192;
                oH[widx] = hp;
                oL[widx] = lp;
                size_t yi = (size_t)(tt * 16 + gb) * 1024 + dir * 512 + (gj >> 1);
                ((unsigned*)YH)[yi] = hp;
                ((unsigned*)YL)[yi] = lp;
            }

            if (s + 1 < Tt) {
                int ttn = dir ? (Tt - 2 - s) : (s + 1);
                const float* gxn = gx + (size_t)(ttn * 16 + gb) * 6144 + dir * 3072;
                xr = __ldg(gxn + gj);
                xz = __ldg(gxn + 1024 + gj);
                xn = __ldg(gxn + 2048 + gj);
            }
        }

        __syncthreads();
        if (tid == 0) {
            red_release_add(bard, 1u);
            unsigned tgt = (unsigned)(s + 1) * 128;
            while (ld_acquire(bard) < tgt) { }
        }
        __syncthreads();
    }
}

// ---------------------------------------------------------------------------
extern "C" void kernel_launch(void* const* d_in, const int* in_sizes, int n_in,
                              void* d_out, int out_size)
{
    const float* inp     = (const float*)d_in[0];
    const float* w_in    = (const float*)d_in[1];
    const float* b_in    = (const float*)d_in[2];
    const float* w_ih_l0 = (const float*)d_in[3];
    const float* w_hh_l0 = (const float*)d_in[4];
    const float* b_ih_l0 = (const float*)d_in[5];
    const float* b_hh_l0 = (const float*)d_in[6];
    const float* w_ih_l1 = (const float*)d_in[7];
    const float* w_hh_l1 = (const float*)d_in[8];
    const float* b_ih_l1 = (const float*)d_in[9];
    const float* b_hh_l1 = (const float*)d_in[10];
    const float* w_out   = (const float*)d_in[11];
    const float* b_out   = (const float*)d_in[12];
    float* out = (float*)d_out;

    float* S = nullptr;
    cudaGetSymbolAddress((void**)&S, g_scratch);
    __nv_bfloat16* BF = nullptr;
    cudaGetSymbolAddress((void**)&BF, g_bf);

    float* GX0  = S + OFF_GX0;
    float* GX1  = S + OFF_GX1;
    float* OUTT = S + OFF_OUTT;
    unsigned* WFH0 = (unsigned*)(S + OFF_WFH0);
    unsigned* WFL0 = (unsigned*)(S + OFF_WFL0);
    unsigned* WFH1 = (unsigned*)(S + OFF_WFH1);
    unsigned* WFL1 = (unsigned*)(S + OFF_WFL1);
    unsigned* HF0  = (unsigned*)(S + OFF_HF0);
    unsigned* HF1  = (unsigned*)(S + OFF_HF1);
    unsigned* BAR0 = (unsigned*)(S + OFF_BAR0);
    unsigned* BAR1 = (unsigned*)(S + OFF_BAR1);

    cudaFuncSetAttribute(gemm_bf16_split_kernel,
                         cudaFuncAttributeMaxDynamicSharedMemorySize, SMEM_GEMM);
    cudaFuncSetAttribute(gru_layer_tc_kernel,
                         cudaFuncAttributeMaxDynamicSharedMemorySize, REC_SMEM);

    const int M = Tt * Bb;  // 8192

    // 1) Mega-prep
    prep_kernel<<<NB_PREP, 256>>>(inp, w_in, w_ih_l0, w_ih_l1, w_out,
                                  w_hh_l0, w_hh_l1, BF,
                                  WFH0, WFL0, WFH1, WFL1, HF0, HF1, BAR0, BAR1);

    // 2) Input projection (bf16 split output)
    gemm_bf16_split_kernel<<<dim3(F / 128, M / 128), 256, SMEM_GEMM>>>(
        BF + BOFF_XH, BF + BOFF_XL, BF + BOFF_WINH, BF + BOFF_WINL, b_in,
        nullptr, BF + BOFF_H0H, BF + BOFF_H0L, M, F, INP);

    // 3) Layer 0 gx
    gemm_bf16_split_kernel<<<dim3(6 * F / 128, M / 128), 256, SMEM_GEMM>>>(
        BF + BOFF_H0H, BF + BOFF_H0L, BF + BOFF_WI0H, BF + BOFF_WI0L, b_ih_l0,
        GX0, nullptr, nullptr, M, 6 * F, F);

    // 4) Layer 0 recurrence  <-- ncu capture slot
    gru_layer_tc_kernel<<<256, 256, REC_SMEM>>>(
        WFH0, WFL0, b_hh_l0, GX0, BF + BOFF_Y0H, BF + BOFF_Y0L, HF0, BAR0);

    // 5) Layer 1 gx
    gemm_bf16_split_kernel<<<dim3(6 * F / 128, M / 128), 256, SMEM_GEMM>>>(
        BF + BOFF_Y0H, BF + BOFF_Y0L, BF + BOFF_WI1H, BF + BOFF_WI1L, b_ih_l1,
        GX1, nullptr, nullptr, M, 6 * F, 2 * F);

    // 6) Layer 1 recurrence
    gru_layer_tc_kernel<<<256, 256, REC_SMEM>>>(
        WFH1, WFL1, b_hh_l1, GX1, BF + BOFF_Y1H, BF + BOFF_Y1L, HF1, BAR1);

    // 7) Output projection
    gemm_bf16_split_kernel<<<dim3(OUTD / 128, M / 128), 256, SMEM_GEMM>>>(
        BF + BOFF_Y1H, BF + BOFF_Y1L, BF + BOFF_WOH, BF + BOFF_WOL, b_out,
        OUTT, nullptr, nullptr, M, OUTD, 2 * F);

    // 8) Final transpose
    transpose_out_kernel<<<dim3(Tt / 32, OUTD / 32, Bb), dim3(32, 8)>>>(OUTT, out);
}

// round 16
// speedup vs baseline: 1.0723x; 1.0230x over previous
#include <cuda_runtime.h>
#include <cuda_bf16.h>
#include <cstddef>

// Problem constants
constexpr int Tt   = 512;
constexpr int Bb   = 16;
constexpr int F    = 1024;
constexpr int INP  = 2048;
constexpr int OUTD = 1024;

// ---------------------------------------------------------------------------
// Float/u32 scratch
// ---------------------------------------------------------------------------
constexpr size_t OFF_GX0  = 0;
constexpr size_t SZ_GX    = (size_t)Tt * Bb * 6 * F;
constexpr size_t OFF_GX1  = OFF_GX0 + SZ_GX;
constexpr size_t OFF_OUTT = OFF_GX1 + SZ_GX;
constexpr size_t SZ_OUTT  = (size_t)Tt * Bb * OUTD;
constexpr size_t SZ_WFp   = (size_t)2 * 64 * 6 * 64 * 32 * 2;   // 3145728
constexpr size_t OFF_WFH0 = OFF_OUTT + SZ_OUTT;
constexpr size_t OFF_WFL0 = OFF_WFH0 + SZ_WFp;
constexpr size_t OFF_WFH1 = OFF_WFL0 + SZ_WFp;
constexpr size_t OFF_WFL1 = OFF_WFH1 + SZ_WFp;
constexpr size_t SZ_HF    = (size_t)2 * 2 * 2 * 64 * 32 * 4;    // 65536
constexpr size_t OFF_HF0  = OFF_WFL1 + SZ_WFp;
constexpr size_t OFF_HF1  = OFF_HF0 + SZ_HF;
constexpr size_t OFF_BAR0 = OFF_HF1 + SZ_HF;    // 64 u32 (2 dirs, 128B apart)
constexpr size_t OFF_BAR1 = OFF_BAR0 + 64;
constexpr size_t SCRATCH_TOTAL = OFF_BAR1 + 64;

__device__ float g_scratch[SCRATCH_TOTAL];

// ---------------------------------------------------------------------------
// bf16 scratch (hi/lo planes)
// ---------------------------------------------------------------------------
constexpr size_t SZ_Xe   = (size_t)Tt * Bb * INP;
constexpr size_t SZ_H0e  = (size_t)Tt * Bb * F;
constexpr size_t SZ_Ye   = (size_t)Tt * Bb * 2 * F;
constexpr size_t SZ_WINe = (size_t)F * INP;
constexpr size_t SZ_WI0e = (size_t)6 * F * F;
constexpr size_t SZ_WI1e = (size_t)6 * F * 2 * F;
constexpr size_t SZ_WOe  = (size_t)OUTD * 2 * F;

constexpr size_t BOFF_XH  = 0;
constexpr size_t BOFF_XL  = BOFF_XH  + SZ_Xe;
constexpr size_t BOFF_H0H = BOFF_XL  + SZ_Xe;
constexpr size_t BOFF_H0L = BOFF_H0H + SZ_H0e;
constexpr size_t BOFF_Y0H = BOFF_H0L + SZ_H0e;
constexpr size_t BOFF_Y0L = BOFF_Y0H + SZ_Ye;
constexpr size_t BOFF_Y1H = BOFF_Y0L + SZ_Ye;
constexpr size_t BOFF_Y1L = BOFF_Y1H + SZ_Ye;
constexpr size_t BOFF_WINH= BOFF_Y1L + SZ_Ye;
constexpr size_t BOFF_WINL= BOFF_WINH+ SZ_WINe;
constexpr size_t BOFF_WI0H= BOFF_WINL+ SZ_WINe;
constexpr size_t BOFF_WI0L= BOFF_WI0H+ SZ_WI0e;
constexpr size_t BOFF_WI1H= BOFF_WI0L+ SZ_WI0e;
constexpr size_t BOFF_WI1L= BOFF_WI1H+ SZ_WI1e;
constexpr size_t BOFF_WOH = BOFF_WI1L+ SZ_WI1e;
constexpr size_t BOFF_WOL = BOFF_WOH + SZ_WOe;
constexpr size_t BF_TOTAL = BOFF_WOL + SZ_WOe;

__device__ __nv_bfloat16 g_bf[BF_TOTAL];

// ---------------------------------------------------------------------------
__device__ __forceinline__ void split_store(float v, __nv_bfloat16* h, __nv_bfloat16* l) {
    __nv_bfloat16 hi = __float2bfloat16(v);
    *h = hi;
    *l = __float2bfloat16(v - __bfloat162float(hi));
}

// ---------------------------------------------------------------------------
// Mega-prep kernel: weight splits + W_hh prepacks + HF/BAR zero + input T/split
// ---------------------------------------------------------------------------
constexpr size_t WSPLIT_N  = SZ_WINe + SZ_WI0e + SZ_WI1e + SZ_WOe;
constexpr int NB_WSPLIT  = (int)(WSPLIT_N / 256);
constexpr int NB_PREPACK = (int)(SZ_WFp / 256);
constexpr int NB_ZERO    = 514;
constexpr int NB_TRANS   = (Tt / 32) * (INP / 32) * Bb;
constexpr int NB_PREP    = NB_WSPLIT + 2 * NB_PREPACK + NB_ZERO + NB_TRANS;

__device__ __forceinline__ void prepack_one(const float* __restrict__ whh,
                                            unsigned* __restrict__ wfh,
                                            unsigned* __restrict__ wfl, size_t i)
{
    size_t i2 = i;
    int r   = (int)(i2 & 1);  i2 >>= 1;
    int l   = (int)(i2 & 31); i2 >>= 5;
    int ks  = (int)(i2 & 63); i2 >>= 6;
    int t   = (int)(i2 % 6);  i2 /= 6;
    int blk = (int)(i2 & 63); i2 >>= 6;
    int d   = (int)i2;
    int g = t >> 1, half = t & 1;
    int row = g * 1024 + blk * 16 + half * 8 + (l >> 2);
    int k   = ks * 16 + r * 8 + (l & 3) * 2;
    float w0 = whh[((size_t)d * 3072 + row) * 1024 + k];
    float w1 = whh[((size_t)d * 3072 + row) * 1024 + k + 1];
    __nv_bfloat16 h0 = __float2bfloat16(w0);
    __nv_bfloat16 h1 = __float2bfloat16(w1);
    __nv_bfloat16 l0 = __float2bfloat16(w0 - __bfloat162float(h0));
    __nv_bfloat16 l1 = __float2bfloat16(w1 - __bfloat162float(h1));
    wfh[i] = ((unsigned)__bfloat16_as_ushort(h1) << 16) | (unsigned)__bfloat16_as_ushort(h0);
    wfl[i] = ((unsigned)__bfloat16_as_ushort(l1) << 16) | (unsigned)__bfloat16_as_ushort(l0);
}

__global__ void __launch_bounds__(256) prep_kernel(
    const float* __restrict__ inp,
    const float* __restrict__ w_in, const float* __restrict__ w_ih_l0,
    const float* __restrict__ w_ih_l1, const float* __restrict__ w_out,
    const float* __restrict__ whh0, const float* __restrict__ whh1,
    __nv_bfloat16* __restrict__ BF,
    unsigned* __restrict__ WFH0, unsigned* __restrict__ WFL0,
    unsigned* __restrict__ WFH1, unsigned* __restrict__ WFL1,
    unsigned* __restrict__ HF0, unsigned* __restrict__ HF1,
    unsigned* __restrict__ BAR0, unsigned* __restrict__ BAR1)
{
    __shared__ float tile[32][33];
    int bid = blockIdx.x;
    int tid = threadIdx.x;

    if (bid < NB_WSPLIT) {
        size_t i = (size_t)bid * 256 + tid;
        const float* src; size_t hoff, loff, idx;
        if (i < SZ_WINe) {
            src = w_in; idx = i; hoff = BOFF_WINH + i; loff = BOFF_WINL + i;
        } else if (i < SZ_WINe + SZ_WI0e) {
            idx = i - SZ_WINe; src = w_ih_l0; hoff = BOFF_WI0H + idx; loff = BOFF_WI0L + idx;
        } else if (i < SZ_WINe + SZ_WI0e + SZ_WI1e) {
            idx = i - SZ_WINe - SZ_WI0e; src = w_ih_l1; hoff = BOFF_WI1H + idx; loff = BOFF_WI1L + idx;
        } else {
            idx = i - SZ_WINe - SZ_WI0e - SZ_WI1e; src = w_out; hoff = BOFF_WOH + idx; loff = BOFF_WOL + idx;
        }
        split_store(src[idx], BF + hoff, BF + loff);
        return;
    }
    bid -= NB_WSPLIT;

    if (bid < NB_PREPACK) {
        prepack_one(whh0, WFH0, WFL0, (size_t)bid * 256 + tid);
        return;
    }
    bid -= NB_PREPACK;

    if (bid < NB_PREPACK) {
        prepack_one(whh1, WFH1, WFL1, (size_t)bid * 256 + tid);
        return;
    }
    bid -= NB_PREPACK;

    if (bid < NB_ZERO) {
        size_t i = (size_t)bid * 256 + tid;
        if (i < SZ_HF) HF0[i] = 0;
        else if (i < 2 * SZ_HF) HF1[i - SZ_HF] = 0;
        else if (i < 2 * SZ_HF + 64) BAR0[i - 2 * SZ_HF] = 0;
        else if (i < 2 * SZ_HF + 128) BAR1[i - 2 * SZ_HF - 64] = 0;
        return;
    }
    bid -= NB_ZERO;

    // Input transpose + split
    {
        int b   = bid >> 10;
        int rem = bid & 1023;
        int i0  = (rem >> 4) * 32;
        int t0  = (rem & 15) * 32;
        int tx = tid & 31, ty = tid >> 5;
#pragma unroll
        for (int j = 0; j < 32; j += 8)
            tile[ty + j][tx] = inp[((size_t)b * INP + (i0 + ty + j)) * Tt + t0 + tx];
        __syncthreads();
        __nv_bfloat16* XH = BF + BOFF_XH;
        __nv_bfloat16* XL = BF + BOFF_XL;
#pragma unroll
        for (int j = 0; j < 32; j += 8) {
            size_t o = ((size_t)(t0 + ty + j) * Bb + b) * INP + i0 + tx;
            split_store(tile[tx][ty + j], XH + o, XL + o);
        }
    }
}

__global__ void transpose_out_kernel(const float* __restrict__ in, float* __restrict__ out) {
    __shared__ float tile[32][33];
    int b  = blockIdx.z;
    int t0 = blockIdx.x * 32;
    int o0 = blockIdx.y * 32;
    int tx = threadIdx.x, ty = threadIdx.y;
#pragma unroll
    for (int j = 0; j < 32; j += 8)
        tile[ty + j][tx] = in[((size_t)(t0 + ty + j) * Bb + b) * OUTD + o0 + tx];
    __syncthreads();
#pragma unroll
    for (int j = 0; j < 32; j += 8)
        out[((size_t)b * OUTD + (o0 + ty + j)) * Tt + t0 + tx] = tile[tx][ty + j];
}

// ---------------------------------------------------------------------------
// Tensor-core split-bf16 GEMM; 128x128 tile, 2 CTAs/SM (TW=40, 80KB smem).
// A planes via cp.async.ca (L1-shared across co-resident CTAs with same bm);
// W planes via cp.async.cg. Pass-outer mma ordering.
// ---------------------------------------------------------------------------
constexpr int TW  = 40;
constexpr int PL  = 128 * TW;
constexpr int GBUF = 4 * PL;
constexpr int SMEM_GEMM = 2 * GBUF * (int)sizeof(__nv_bfloat16);  // 81920

__device__ __forceinline__ void cpa16_cg(void* sdst, const void* gsrc) {
    unsigned s = (unsigned)__cvta_generic_to_shared(sdst);
    asm volatile("cp.async.cg.shared.global [%0], [%1], 16;\n" :: "r"(s), "l"(gsrc));
}
__device__ __forceinline__ void cpa16_ca(void* sdst, const void* gsrc) {
    unsigned s = (unsigned)__cvta_generic_to_shared(sdst);
    asm volatile("cp.async.ca.shared.global [%0], [%1], 16;\n" :: "r"(s), "l"(gsrc));
}
__device__ __forceinline__ void cpa_commit() {
    asm volatile("cp.async.commit_group;\n" ::);
}
__device__ __forceinline__ void cpa_wait0() {
    asm volatile("cp.async.wait_group 0;\n" ::);
}
__device__ __forceinline__ void mma_bf16(float* c, const unsigned* a, const unsigned* b) {
    asm volatile(
        "mma.sync.aligned.m16n8k16.row.col.f32.bf16.bf16.f32 "
        "{%0,%1,%2,%3},{%4,%5,%6,%7},{%8,%9},{%0,%1,%2,%3};\n"
        : "+f"(c[0]), "+f"(c[1]), "+f"(c[2]), "+f"(c[3])
        : "r"(a[0]), "r"(a[1]), "r"(a[2]), "r"(a[3]), "r"(b[0]), "r"(b[1]));
}
__device__ __forceinline__ void ldsm4(unsigned* r, const __nv_bfloat16* p) {
    unsigned a = (unsigned)__cvta_generic_to_shared(p);
    asm volatile("ldmatrix.sync.aligned.m8n8.x4.shared.b16 {%0,%1,%2,%3},[%4];\n"
        : "=r"(r[0]), "=r"(r[1]), "=r"(r[2]), "=r"(r[3]) : "r"(a));
}
__device__ __forceinline__ void ldsm2(unsigned* r, const __nv_bfloat16* p) {
    unsigned a = (unsigned)__cvta_generic_to_shared(p);
    asm volatile("ldmatrix.sync.aligned.m8n8.x2.shared.b16 {%0,%1},[%2];\n"
        : "=r"(r[0]), "=r"(r[1]) : "r"(a));
}

__global__ void __launch_bounds__(256, 2) gemm_bf16_split_kernel(
    const __nv_bfloat16* __restrict__ Ah, const __nv_bfloat16* __restrict__ Al,
    const __nv_bfloat16* __restrict__ Wh, const __nv_bfloat16* __restrict__ Wl,
    const float* __restrict__ bias,
    float* __restrict__ C,
    __nv_bfloat16* __restrict__ CH, __nv_bfloat16* __restrict__ CL,
    int M, int N, int K)
{
    extern __shared__ __nv_bfloat16 smx[];
    const int tid = threadIdx.x;
    const int bm = blockIdx.y * 128, bn = blockIdx.x * 128;
    const int lane = tid & 31, wid = tid >> 5;
    const int wm = wid & 1, wn = wid >> 1;
    const int g = lane >> 2, t = lane & 3;

    float acc[4][4][4];
#pragma unroll
    for (int i = 0; i < 4; ++i)
#pragma unroll
        for (int j = 0; j < 4; ++j)
#pragma unroll
            for (int q = 0; q < 4; ++q) acc[i][j][q] = 0.f;

    const int r0 = tid >> 2;
    const int c0 = (tid & 3) * 8;
    const int nk = K / 32;

    const int aOff = (wm * 64 + (lane & 7) + ((lane >> 3) & 1) * 8) * TW + (lane >> 4) * 8;
    const int lb = lane & 15;
    const int bOff = (wn * 32 + (lb & 7)) * TW + ((lb >> 3) & 1) * 8;

    {
        __nv_bfloat16* s = smx;
#pragma unroll
        for (int p = 0; p < 2; ++p) {
            int row = r0 + p * 64;
            size_t ga = (size_t)(bm + row) * K + c0;
            size_t gw = (size_t)(bn + row) * K + c0;
            int so = row * TW + c0;
            cpa16_ca(s + 0 * PL + so, Ah + ga);
            cpa16_ca(s + 1 * PL + so, Al + ga);
            cpa16_cg(s + 2 * PL + so, Wh + gw);
            cpa16_cg(s + 3 * PL + so, Wl + gw);
        }
        cpa_commit();
    }

    for (int kt = 0; kt < nk; ++kt) {
        cpa_wait0();
        __syncthreads();

        if (kt + 1 < nk) {
            __nv_bfloat16* s = smx + ((kt + 1) & 1) * GBUF;
            int k0 = (kt + 1) * 32;
#pragma unroll
            for (int p = 0; p < 2; ++p) {
                int row = r0 + p * 64;
                size_t ga = (size_t)(bm + row) * K + k0 + c0;
                size_t gw = (size_t)(bn + row) * K + k0 + c0;
                int so = row * TW + c0;
                cpa16_ca(s + 0 * PL + so, Ah + ga);
                cpa16_ca(s + 1 * PL + so, Al + ga);
                cpa16_cg(s + 2 * PL + so, Wh + gw);
                cpa16_cg(s + 3 * PL + so, Wl + gw);
            }
            cpa_commit();
        }

        const __nv_bfloat16* sb = smx + (kt & 1) * GBUF;

#pragma unroll
        for (int ks = 0; ks < 2; ++ks) {
            unsigned aH[4][4], aL[4][4], bH[4][2], bL[4][2];
#pragma unroll
            for (int i = 0; i < 4; ++i) {
                int off = aOff + i * 16 * TW + ks * 16;
                ldsm4(aH[i], sb + 0 * PL + off);
                ldsm4(aL[i], sb + 1 * PL + off);
            }
#pragma unroll
            for (int j = 0; j < 4; ++j) {
                int off = bOff + j * 8 * TW + ks * 16;
                ldsm2(bH[j], sb + 2 * PL + off);
                ldsm2(bL[j], sb + 3 * PL + off);
            }
            // Pass-outer ordering: consecutive mma hit different accumulators
#pragma unroll
            for (int i = 0; i < 4; ++i)
#pragma unroll
                for (int j = 0; j < 4; ++j)
                    mma_bf16(acc[i][j], aH[i], bH[j]);
#pragma unroll
            for (int i = 0; i < 4; ++i)
#pragma unroll
                for (int j = 0; j < 4; ++j)
                    mma_bf16(acc[i][j], aH[i], bL[j]);
#pragma unroll
            for (int i = 0; i < 4; ++i)
#pragma unroll
                for (int j = 0; j < 4; ++j)
                    mma_bf16(acc[i][j], aL[i], bH[j]);
        }
    }

#pragma unroll
    for (int i = 0; i < 4; ++i) {
        int row0 = bm + wm * 64 + i * 16 + g;
#pragma unroll
        for (int j = 0; j < 4; ++j) {
            int col = bn + wn * 32 + j * 8 + t * 2;
            float b0 = bias[col], b1 = bias[col + 1];
            float v00 = acc[i][j][0] + b0, v01 = acc[i][j][1] + b1;
            float v10 = acc[i][j][2] + b0, v11 = acc[i][j][3] + b1;
            if (CH) {
                size_t p0 = (size_t)row0 * N + col;
                size_t p1 = (size_t)(row0 + 8) * N + col;
                __nv_bfloat16 h00 = __float2bfloat16(v00), h01 = __float2bfloat16(v01);
                __nv_bfloat16 h10 = __float2bfloat16(v10), h11 = __float2bfloat16(v11);
                *(__nv_bfloat162*)(CH + p0) = __nv_bfloat162(h00, h01);
                *(__nv_bfloat162*)(CH + p1) = __nv_bfloat162(h10, h11);
                *(__nv_bfloat162*)(CL + p0) = __nv_bfloat162(
                    __float2bfloat16(v00 - __bfloat162float(h00)),
                    __float2bfloat16(v01 - __bfloat162float(h01)));
                *(__nv_bfloat162*)(CL + p1) = __nv_bfloat162(
                    __float2bfloat16(v10 - __bfloat162float(h10)),
                    __float2bfloat16(v11 - __bfloat162float(h11)));
            } else {
                *(float2*)(C + (size_t)row0 * N + col) = make_float2(v00, v01);
                *(float2*)(C + (size_t)(row0 + 8) * N + col) = make_float2(v10, v11);
            }
        }
    }
}

// ---------------------------------------------------------------------------
// Persistent tensor-core bidirectional GRU layer (R7 protocol, MUFU gates,
// pass-outer mma ordering, depth-2 h-fragment prefetch).
// 256 blocks (128/dir), 8 units/block, 2 CTAs/SM.
// ---------------------------------------------------------------------------
constexpr int WSL_U32 = 3 * 64 * 32 * 2;
constexpr int REC_SMEM = WSL_U32 * 4 + (8 * 3 * 32 * 4) * 4;

__device__ __forceinline__ unsigned ld_acquire(const unsigned* p) {
    unsigned v;
    asm volatile("ld.global.acquire.gpu.u32 %0, [%1];" : "=r"(v) : "l"(p) : "memory");
    return v;
}
__device__ __forceinline__ void red_release_add(unsigned* p, unsigned v) {
    asm volatile("red.release.gpu.global.add.u32 [%0], %1;" :: "l"(p), "r"(v) : "memory");
}
__device__ __forceinline__ float fast_sigmoid(float x) {
    return 1.f / (1.f + __expf(-x));
}
__device__ __forceinline__ float fast_tanh(float x) {
    float e = __expf(2.f * x);
    return (e - 1.f) / (e + 1.f);
}

__global__ void __launch_bounds__(256, 2) gru_layer_tc_kernel(
    const unsigned* __restrict__ WFH, const unsigned* __restrict__ WFL,
    const float* __restrict__ bhh,
    const float* __restrict__ gx,
    __nv_bfloat16* __restrict__ YH, __nv_bfloat16* __restrict__ YL,
    unsigned* __restrict__ HF,
    unsigned* __restrict__ bar)
{
    extern __shared__ unsigned smu[];
    unsigned* wsL = smu;
    float* red = (float*)(smu + WSL_U32);

    const int tid  = threadIdx.x;
    const int dir  = blockIdx.x >> 7;
    const int blk  = blockIdx.x & 127;
    const int B16  = blk >> 1;
    const int half = blk & 1;
    const int u0   = blk * 8;
    const int lane = tid & 31, w = tid >> 5;
    unsigned* bard = bar + dir * 32;

    {
        const unsigned* lbase = WFL + (size_t)(dir * 64 + B16) * (6 * 4096);
#pragma unroll
        for (int t = 0; t < 3; ++t) {
            const uint4* src = (const uint4*)(lbase + (t * 2 + half) * 4096);
            uint4* dst = (uint4*)(wsL + t * 4096);
            for (int i = tid; i < 1024; i += 256) dst[i] = src[i];
        }
    }

    unsigned bHreg[8][3][2];
    {
        const unsigned* hbase = WFH + (size_t)(dir * 64 + B16) * (6 * 4096);
#pragma unroll
        for (int kk = 0; kk < 8; ++kk) {
            int ks = w * 8 + kk;
#pragma unroll
            for (int t = 0; t < 3; ++t) {
                uint2 v = *(const uint2*)(hbase + (t * 2 + half) * 4096 + ks * 64 + lane * 2);
                bHreg[kk][t][0] = v.x;
                bHreg[kk][t][1] = v.y;
            }
        }
    }

    const bool gactive = tid < 128;
    const int gb = tid >> 3;
    const int gu = tid & 7;
    const int gj = u0 + gu;
    float br = 0.f, bz = 0.f, bn2 = 0.f;
    if (gactive) {
        br  = bhh[dir * 3072 + gj];
        bz  = bhh[dir * 3072 + 1024 + gj];
        bn2 = bhh[dir * 3072 + 2048 + gj];
    }
    float hprev = 0.f;

    const int ksb   = blk >> 1;
    const int wlane = ((gb & 7) << 2) + (gu >> 1);
    const int wreg  = (half ? 2 : 0) + ((gb >= 8) ? 1 : 0);
    const int widx  = (ksb * 32 + wlane) * 4 + wreg;
    const int foff  = wlane * 4 + (gu & 1) + ((gb >= 8) ? 2 : 0);

    float xr = 0.f, xz = 0.f, xn = 0.f;
    if (gactive) {
        int tt0 = dir ? (Tt - 1) : 0;
        const float* gxp = gx + (size_t)(tt0 * 16 + gb) * 6144 + dir * 3072;
        xr = __ldg(gxp + gj);
        xz = __ldg(gxp + 1024 + gj);
        xn = __ldg(gxp + 2048 + gj);
    }

    __syncthreads();

    for (int s = 0; s < Tt; ++s) {
        const int cur = s & 1, nxt = cur ^ 1;
        const int tt  = dir ? (Tt - 1 - s) : s;

        float acc[3][4];
#pragma unroll
        for (int t = 0; t < 3; ++t)
#pragma unroll
            for (int q = 0; q < 4; ++q) acc[t][q] = 0.f;

        const unsigned* hfH = HF + ((size_t)(cur * 2 + dir) * 2 + 0) * 8192;
        const unsigned* hfL = HF + ((size_t)(cur * 2 + dir) * 2 + 1) * 8192;

        // Depth-2 software prefetch on h fragments
        uint4 AHv = __ldcg((const uint4*)(hfH + ((w * 8) * 32 + lane) * 4));
        uint4 ALv = __ldcg((const uint4*)(hfL + ((w * 8) * 32 + lane) * 4));

#pragma unroll
        for (int kk = 0; kk < 8; ++kk) {
            unsigned aH[4] = {AHv.x, AHv.y, AHv.z, AHv.w};
            unsigned aL[4] = {ALv.x, ALv.y, ALv.z, ALv.w};
            if (kk < 7) {
                int ksn = w * 8 + kk + 1;
                AHv = __ldcg((const uint4*)(hfH + (ksn * 32 + lane) * 4));
                ALv = __ldcg((const uint4*)(hfL + (ksn * 32 + lane) * 4));
            }
            int ks = w * 8 + kk;
            // Pass-outer ordering: consecutive mma hit different acc[t]
#pragma unroll
            for (int t = 0; t < 3; ++t)
                mma_bf16(acc[t], aH, bHreg[kk][t]);
#pragma unroll
            for (int t = 0; t < 3; ++t)
                mma_bf16(acc[t], aL, bHreg[kk][t]);
#pragma unroll
            for (int t = 0; t < 3; ++t) {
                uint2 bLv = *(const uint2*)&wsL[t * 4096 + ks * 64 + lane * 2];
                unsigned bL[2] = {bLv.x, bLv.y};
                mma_bf16(acc[t], aH, bL);
            }
        }
#pragma unroll
        for (int t = 0; t < 3; ++t)
            *(float4*)&red[((w * 3 + t) * 32 + lane) * 4] =
                make_float4(acc[t][0], acc[t][1], acc[t][2], acc[t][3]);
        __syncthreads();

        if (gactive) {
            float ghr = br, ghz = bz, ghn = bn2;
#pragma unroll
            for (int ww = 0; ww < 8; ++ww) {
                ghr += red[(ww * 3 + 0) * 128 + foff];
                ghz += red[(ww * 3 + 1) * 128 + foff];
                ghn += red[(ww * 3 + 2) * 128 + foff];
            }
            float r = fast_sigmoid(xr + ghr);
            float z = fast_sigmoid(xz + ghz);
            float n = fast_tanh(xn + r * ghn);
            float hnew = (1.f - z) * n + z * hprev;
            hprev = hnew;

            __nv_bfloat16 hhi = __float2bfloat16(hnew);
            float rlo = hnew - __bfloat162float(hhi);
            __nv_bfloat16 hlo = __float2bfloat16(rlo);
            unsigned vh = (unsigned)__bfloat16_as_ushort(hhi);
            unsigned vl = (unsigned)__bfloat16_as_ushort(hlo);
            unsigned phh = __shfl_down_sync(0xffffffffu, vh, 1);
            unsigned pll = __shfl_down_sync(0xffffffffu, vl, 1);
            if ((gu & 1) == 0) {
                unsigned hp = (phh << 16) | vh;
                unsigned lp = (pll << 16) | vl;
                unsigned* oH = HF + ((size_t)(nxt * 2 + dir) * 2 + 0) * 8192;
                unsigned* oL = HF + ((size_t)(nxt * 2 + dir) * 2 + 1) * 8192;
                oH[widx] = hp;
                oL[widx] = lp;
                size_t yi = (size_t)(tt * 16 + gb) * 1024 + dir * 512 + (gj >> 1);
                ((unsigned*)YH)[yi] = hp;
                ((unsigned*)YL)[yi] = lp;
            }

            if (s + 1 < Tt) {
                int ttn = dir ? (Tt - 2 - s) : (s + 1);
                const float* gxn = gx + (size_t)(ttn * 16 + gb) * 6144 + dir * 3072;
                xr = __ldg(gxn + gj);
                xz = __ldg(gxn + 1024 + gj);
                xn = __ldg(gxn + 2048 + gj);
            }
        }

        __syncthreads();
        if (tid == 0) {
            red_release_add(bard, 1u);
            unsigned tgt = (unsigned)(s + 1) * 128;
            while (ld_acquire(bard) < tgt) { }
        }
        __syncthreads();
    }
}

// ---------------------------------------------------------------------------
extern "C" void kernel_launch(void* const* d_in, const int* in_sizes, int n_in,
                              void* d_out, int out_size)
{
    const float* inp     = (const float*)d_in[0];
    const float* w_in    = (const float*)d_in[1];
    const float* b_in    = (const float*)d_in[2];
    const float* w_ih_l0 = (const float*)d_in[3];
    const float* w_hh_l0 = (const float*)d_in[4];
    const float* b_ih_l0 = (const float*)d_in[5];
    const float* b_hh_l0 = (const float*)d_in[6];
    const float* w_ih_l1 = (const float*)d_in[7];
    const float* w_hh_l1 = (const float*)d_in[8];
    const float* b_ih_l1 = (const float*)d_in[9];
    const float* b_hh_l1 = (const float*)d_in[10];
    const float* w_out   = (const float*)d_in[11];
    const float* b_out   = (const float*)d_in[12];
    float* out = (float*)d_out;

    float* S = nullptr;
    cudaGetSymbolAddress((void**)&S, g_scratch);
    __nv_bfloat16* BF = nullptr;
    cudaGetSymbolAddress((void**)&BF, g_bf);

    float* GX0  = S + OFF_GX0;
    float* GX1  = S + OFF_GX1;
    float* OUTT = S + OFF_OUTT;
    unsigned* WFH0 = (unsigned*)(S + OFF_WFH0);
    unsigned* WFL0 = (unsigned*)(S + OFF_WFL0);
    unsigned* WFH1 = (unsigned*)(S + OFF_WFH1);
    unsigned* WFL1 = (unsigned*)(S + OFF_WFL1);
    unsigned* HF0  = (unsigned*)(S + OFF_HF0);
    unsigned* HF1  = (unsigned*)(S + OFF_HF1);
    unsigned* BAR0 = (unsigned*)(S + OFF_BAR0);
    unsigned* BAR1 = (unsigned*)(S + OFF_BAR1);

    cudaFuncSetAttribute(gemm_bf16_split_kernel,
                         cudaFuncAttributeMaxDynamicSharedMemorySize, SMEM_GEMM);
    cudaFuncSetAttribute(gru_layer_tc_kernel,
                         cudaFuncAttributeMaxDynamicSharedMemorySize, REC_SMEM);

    const int M = Tt * Bb;  // 8192

    // 1) Mega-prep
    prep_kernel<<<NB_PREP, 256>>>(inp, w_in, w_ih_l0, w_ih_l1, w_out,
                                  w_hh_l0, w_hh_l1, BF,
                                  WFH0, WFL0, WFH1, WFL1, HF0, HF1, BAR0, BAR1);

    // 2) Input projection (bf16 split output)
    gemm_bf16_split_kernel<<<dim3(F / 128, M / 128), 256, SMEM_GEMM>>>(
        BF + BOFF_XH, BF + BOFF_XL, BF + BOFF_WINH, BF + BOFF_WINL, b_in,
        nullptr, BF + BOFF_H0H, BF + BOFF_H0L, M, F, INP);

    // 3) Layer 0 gx
    gemm_bf16_split_kernel<<<dim3(6 * F / 128, M / 128), 256, SMEM_GEMM>>>(
        BF + BOFF_H0H, BF + BOFF_H0L, BF + BOFF_WI0H, BF + BOFF_WI0L, b_ih_l0,
        GX0, nullptr, nullptr, M, 6 * F, F);

    // 4) Layer 0 recurrence  <-- ncu capture slot
    gru_layer_tc_kernel<<<256, 256, REC_SMEM>>>(
        WFH0, WFL0, b_hh_l0, GX0, BF + BOFF_Y0H, BF + BOFF_Y0L, HF0, BAR0);

    // 5) Layer 1 gx
    gemm_bf16_split_kernel<<<dim3(6 * F / 128, M / 128), 256, SMEM_GEMM>>>(
        BF + BOFF_Y0H, BF + BOFF_Y0L, BF + BOFF_WI1H, BF + BOFF_WI1L, b_ih_l1,
        GX1, nullptr, nullptr, M, 6 * F, 2 * F);

    // 6) Layer 1 recurrence
    gru_layer_tc_kernel<<<256, 256, REC_SMEM>>>(
        WFH1, WFL1, b_hh_l1, GX1, BF + BOFF_Y1H, BF + BOFF_Y1L, HF1, BAR1);

    // 7) Output projection
    gemm_bf16_split_kernel<<<dim3(OUTD / 128, M / 128), 256, SMEM_GEMM>>>(
        BF + BOFF_Y1H, BF + BOFF_Y1L, BF + BOFF_WOH, BF + BOFF_WOL, b_out,
        OUTT, nullptr, nullptr, M, OUTD, 2 * F);

    // 8) Final transpose
    transpose_out_kernel<<<dim3(Tt / 32, OUTD / 32, Bb), dim3(32, 8)>>>(OUTT, out);
}

// round 17
// speedup vs baseline: 1.0729x; 1.0005x over previous
#include <cuda_runtime.h>
#include <cuda_bf16.h>
#include <cstddef>

// Problem constants
constexpr int Tt   = 512;
constexpr int Bb   = 16;
constexpr int F    = 1024;
constexpr int INP  = 2048;
constexpr int OUTD = 1024;

// ---------------------------------------------------------------------------
// Float/u32 scratch
// ---------------------------------------------------------------------------
constexpr size_t OFF_GX0  = 0;
constexpr size_t SZ_GX    = (size_t)Tt * Bb * 6 * F;
constexpr size_t OFF_GX1  = OFF_GX0 + SZ_GX;
constexpr size_t OFF_OUTT = OFF_GX1 + SZ_GX;
constexpr size_t SZ_OUTT  = (size_t)Tt * Bb * OUTD;
constexpr size_t SZ_WFp   = (size_t)2 * 64 * 6 * 64 * 32 * 2;   // 3145728
constexpr size_t OFF_WFH0 = OFF_OUTT + SZ_OUTT;
constexpr size_t OFF_WFL0 = OFF_WFH0 + SZ_WFp;
constexpr size_t OFF_WFH1 = OFF_WFL0 + SZ_WFp;
constexpr size_t OFF_WFL1 = OFF_WFH1 + SZ_WFp;
constexpr size_t SZ_HF    = (size_t)2 * 2 * 2 * 64 * 32 * 4;    // 65536
constexpr size_t OFF_HF0  = OFF_WFL1 + SZ_WFp;
constexpr size_t OFF_HF1  = OFF_HF0 + SZ_HF;
constexpr size_t OFF_BAR0 = OFF_HF1 + SZ_HF;    // 64 u32 (2 dirs, 128B apart)
constexpr size_t OFF_BAR1 = OFF_BAR0 + 64;
constexpr size_t SCRATCH_TOTAL = OFF_BAR1 + 64;

__device__ float g_scratch[SCRATCH_TOTAL];

// ---------------------------------------------------------------------------
// bf16 scratch (hi/lo planes)
// ---------------------------------------------------------------------------
constexpr size_t SZ_Xe   = (size_t)Tt * Bb * INP;
constexpr size_t SZ_H0e  = (size_t)Tt * Bb * F;
constexpr size_t SZ_Ye   = (size_t)Tt * Bb * 2 * F;
constexpr size_t SZ_WINe = (size_t)F * INP;
constexpr size_t SZ_WI0e = (size_t)6 * F * F;
constexpr size_t SZ_WI1e = (size_t)6 * F * 2 * F;
constexpr size_t SZ_WOe  = (size_t)OUTD * 2 * F;

constexpr size_t BOFF_XH  = 0;
constexpr size_t BOFF_XL  = BOFF_XH  + SZ_Xe;
constexpr size_t BOFF_H0H = BOFF_XL  + SZ_Xe;
constexpr size_t BOFF_H0L = BOFF_H0H + SZ_H0e;
constexpr size_t BOFF_Y0H = BOFF_H0L + SZ_H0e;
constexpr size_t BOFF_Y0L = BOFF_Y0H + SZ_Ye;
constexpr size_t BOFF_Y1H = BOFF_Y0L + SZ_Ye;
constexpr size_t BOFF_Y1L = BOFF_Y1H + SZ_Ye;
constexpr size_t BOFF_WINH= BOFF_Y1L + SZ_Ye;
constexpr size_t BOFF_WINL= BOFF_WINH+ SZ_WINe;
constexpr size_t BOFF_WI0H= BOFF_WINL+ SZ_WINe;
constexpr size_t BOFF_WI0L= BOFF_WI0H+ SZ_WI0e;
constexpr size_t BOFF_WI1H= BOFF_WI0L+ SZ_WI0e;
constexpr size_t BOFF_WI1L= BOFF_WI1H+ SZ_WI1e;
constexpr size_t BOFF_WOH = BOFF_WI1L+ SZ_WI1e;
constexpr size_t BOFF_WOL = BOFF_WOH + SZ_WOe;
constexpr size_t BF_TOTAL = BOFF_WOL + SZ_WOe;

__device__ __nv_bfloat16 g_bf[BF_TOTAL];

// ---------------------------------------------------------------------------
__device__ __forceinline__ void split_store(float v, __nv_bfloat16* h, __nv_bfloat16* l) {
    __nv_bfloat16 hi = __float2bfloat16(v);
    *h = hi;
    *l = __float2bfloat16(v - __bfloat162float(hi));
}

// ---------------------------------------------------------------------------
// Mega-prep kernel: weight splits + W_hh prepacks + HF/BAR zero + input T/split
// ---------------------------------------------------------------------------
constexpr size_t WSPLIT_N  = SZ_WINe + SZ_WI0e + SZ_WI1e + SZ_WOe;
constexpr int NB_WSPLIT  = (int)(WSPLIT_N / 256);
constexpr int NB_PREPACK = (int)(SZ_WFp / 256);
constexpr int NB_ZERO    = 514;
constexpr int NB_TRANS   = (Tt / 32) * (INP / 32) * Bb;
constexpr int NB_PREP    = NB_WSPLIT + 2 * NB_PREPACK + NB_ZERO + NB_TRANS;

__device__ __forceinline__ void prepack_one(const float* __restrict__ whh,
                                            unsigned* __restrict__ wfh,
                                            unsigned* __restrict__ wfl, size_t i)
{
    size_t i2 = i;
    int r   = (int)(i2 & 1);  i2 >>= 1;
    int l   = (int)(i2 & 31); i2 >>= 5;
    int ks  = (int)(i2 & 63); i2 >>= 6;
    int t   = (int)(i2 % 6);  i2 /= 6;
    int blk = (int)(i2 & 63); i2 >>= 6;
    int d   = (int)i2;
    int g = t >> 1, half = t & 1;
    int row = g * 1024 + blk * 16 + half * 8 + (l >> 2);
    int k   = ks * 16 + r * 8 + (l & 3) * 2;
    float w0 = whh[((size_t)d * 3072 + row) * 1024 + k];
    float w1 = whh[((size_t)d * 3072 + row) * 1024 + k + 1];
    __nv_bfloat16 h0 = __float2bfloat16(w0);
    __nv_bfloat16 h1 = __float2bfloat16(w1);
    __nv_bfloat16 l0 = __float2bfloat16(w0 - __bfloat162float(h0));
    __nv_bfloat16 l1 = __float2bfloat16(w1 - __bfloat162float(h1));
    wfh[i] = ((unsigned)__bfloat16_as_ushort(h1) << 16) | (unsigned)__bfloat16_as_ushort(h0);
    wfl[i] = ((unsigned)__bfloat16_as_ushort(l1) << 16) | (unsigned)__bfloat16_as_ushort(l0);
}

__global__ void __launch_bounds__(256) prep_kernel(
    const float* __restrict__ inp,
    const float* __restrict__ w_in, const float* __restrict__ w_ih_l0,
    const float* __restrict__ w_ih_l1, const float* __restrict__ w_out,
    const float* __restrict__ whh0, const float* __restrict__ whh1,
    __nv_bfloat16* __restrict__ BF,
    unsigned* __restrict__ WFH0, unsigned* __restrict__ WFL0,
    unsigned* __restrict__ WFH1, unsigned* __restrict__ WFL1,
    unsigned* __restrict__ HF0, unsigned* __restrict__ HF1,
    unsigned* __restrict__ BAR0, unsigned* __restrict__ BAR1)
{
    __shared__ float tile[32][33];
    int bid = blockIdx.x;
    int tid = threadIdx.x;

    if (bid < NB_WSPLIT) {
        size_t i = (size_t)bid * 256 + tid;
        const float* src; size_t hoff, loff, idx;
        if (i < SZ_WINe) {
            src = w_in; idx = i; hoff = BOFF_WINH + i; loff = BOFF_WINL + i;
        } else if (i < SZ_WINe + SZ_WI0e) {
            idx = i - SZ_WINe; src = w_ih_l0; hoff = BOFF_WI0H + idx; loff = BOFF_WI0L + idx;
        } else if (i < SZ_WINe + SZ_WI0e + SZ_WI1e) {
            idx = i - SZ_WINe - SZ_WI0e; src = w_ih_l1; hoff = BOFF_WI1H + idx; loff = BOFF_WI1L + idx;
        } else {
            idx = i - SZ_WINe - SZ_WI0e - SZ_WI1e; src = w_out; hoff = BOFF_WOH + idx; loff = BOFF_WOL + idx;
        }
        split_store(src[idx], BF + hoff, BF + loff);
        return;
    }
    bid -= NB_WSPLIT;

    if (bid < NB_PREPACK) {
        prepack_one(whh0, WFH0, WFL0, (size_t)bid * 256 + tid);
        return;
    }
    bid -= NB_PREPACK;

    if (bid < NB_PREPACK) {
        prepack_one(whh1, WFH1, WFL1, (size_t)bid * 256 + tid);
        return;
    }
    bid -= NB_PREPACK;

    if (bid < NB_ZERO) {
        size_t i = (size_t)bid * 256 + tid;
        if (i < SZ_HF) HF0[i] = 0;
        else if (i < 2 * SZ_HF) HF1[i - SZ_HF] = 0;
        else if (i < 2 * SZ_HF + 64) BAR0[i - 2 * SZ_HF] = 0;
        else if (i < 2 * SZ_HF + 128) BAR1[i - 2 * SZ_HF - 64] = 0;
        return;
    }
    bid -= NB_ZERO;

    // Input transpose + split
    {
        int b   = bid >> 10;
        int rem = bid & 1023;
        int i0  = (rem >> 4) * 32;
        int t0  = (rem & 15) * 32;
        int tx = tid & 31, ty = tid >> 5;
#pragma unroll
        for (int j = 0; j < 32; j += 8)
            tile[ty + j][tx] = inp[((size_t)b * INP + (i0 + ty + j)) * Tt + t0 + tx];
        __syncthreads();
        __nv_bfloat16* XH = BF + BOFF_XH;
        __nv_bfloat16* XL = BF + BOFF_XL;
#pragma unroll
        for (int j = 0; j < 32; j += 8) {
            size_t o = ((size_t)(t0 + ty + j) * Bb + b) * INP + i0 + tx;
            split_store(tile[tx][ty + j], XH + o, XL + o);
        }
    }
}

__global__ void transpose_out_kernel(const float* __restrict__ in, float* __restrict__ out) {
    __shared__ float tile[32][33];
    int b  = blockIdx.z;
    int t0 = blockIdx.x * 32;
    int o0 = blockIdx.y * 32;
    int tx = threadIdx.x, ty = threadIdx.y;
#pragma unroll
    for (int j = 0; j < 32; j += 8)
        tile[ty + j][tx] = in[((size_t)(t0 + ty + j) * Bb + b) * OUTD + o0 + tx];
    __syncthreads();
#pragma unroll
    for (int j = 0; j < 32; j += 8)
        out[((size_t)b * OUTD + (o0 + ty + j)) * Tt + t0 + tx] = tile[tx][ty + j];
}

// ---------------------------------------------------------------------------
// Tensor-core split-bf16 GEMM; 128x128 tile, 2 CTAs/SM (TW=40, 80KB smem).
// A planes via cp.async.ca; W planes via cp.async.cg. Pass-outer mma ordering.
// ---------------------------------------------------------------------------
constexpr int TW  = 40;
constexpr int PL  = 128 * TW;
constexpr int GBUF = 4 * PL;
constexpr int SMEM_GEMM = 2 * GBUF * (int)sizeof(__nv_bfloat16);  // 81920

__device__ __forceinline__ void cpa16_cg(void* sdst, const void* gsrc) {
    unsigned s = (unsigned)__cvta_generic_to_shared(sdst);
    asm volatile("cp.async.cg.shared.global [%0], [%1], 16;\n" :: "r"(s), "l"(gsrc));
}
__device__ __forceinline__ void cpa16_ca(void* sdst, const void* gsrc) {
    unsigned s = (unsigned)__cvta_generic_to_shared(sdst);
    asm volatile("cp.async.ca.shared.global [%0], [%1], 16;\n" :: "r"(s), "l"(gsrc));
}
__device__ __forceinline__ void cpa_commit() {
    asm volatile("cp.async.commit_group;\n" ::);
}
__device__ __forceinline__ void cpa_wait0() {
    asm volatile("cp.async.wait_group 0;\n" ::);
}
__device__ __forceinline__ void mma_bf16(float* c, const unsigned* a, const unsigned* b) {
    asm volatile(
        "mma.sync.aligned.m16n8k16.row.col.f32.bf16.bf16.f32 "
        "{%0,%1,%2,%3},{%4,%5,%6,%7},{%8,%9},{%0,%1,%2,%3};\n"
        : "+f"(c[0]), "+f"(c[1]), "+f"(c[2]), "+f"(c[3])
        : "r"(a[0]), "r"(a[1]), "r"(a[2]), "r"(a[3]), "r"(b[0]), "r"(b[1]));
}
__device__ __forceinline__ void ldsm4(unsigned* r, const __nv_bfloat16* p) {
    unsigned a = (unsigned)__cvta_generic_to_shared(p);
    asm volatile("ldmatrix.sync.aligned.m8n8.x4.shared.b16 {%0,%1,%2,%3},[%4];\n"
        : "=r"(r[0]), "=r"(r[1]), "=r"(r[2]), "=r"(r[3]) : "r"(a));
}
__device__ __forceinline__ void ldsm2(unsigned* r, const __nv_bfloat16* p) {
    unsigned a = (unsigned)__cvta_generic_to_shared(p);
    asm volatile("ldmatrix.sync.aligned.m8n8.x2.shared.b16 {%0,%1},[%2];\n"
        : "=r"(r[0]), "=r"(r[1]) : "r"(a));
}

__global__ void __launch_bounds__(256, 2) gemm_bf16_split_kernel(
    const __nv_bfloat16* __restrict__ Ah, const __nv_bfloat16* __restrict__ Al,
    const __nv_bfloat16* __restrict__ Wh, const __nv_bfloat16* __restrict__ Wl,
    const float* __restrict__ bias,
    float* __restrict__ C,
    __nv_bfloat16* __restrict__ CH, __nv_bfloat16* __restrict__ CL,
    int M, int N, int K)
{
    extern __shared__ __nv_bfloat16 smx[];
    const int tid = threadIdx.x;
    const int bm = blockIdx.y * 128, bn = blockIdx.x * 128;
    const int lane = tid & 31, wid = tid >> 5;
    const int wm = wid & 1, wn = wid >> 1;
    const int g = lane >> 2, t = lane & 3;

    float acc[4][4][4];
#pragma unroll
    for (int i = 0; i < 4; ++i)
#pragma unroll
        for (int j = 0; j < 4; ++j)
#pragma unroll
            for (int q = 0; q < 4; ++q) acc[i][j][q] = 0.f;

    const int r0 = tid >> 2;
    const int c0 = (tid & 3) * 8;
    const int nk = K / 32;

    const int aOff = (wm * 64 + (lane & 7) + ((lane >> 3) & 1) * 8) * TW + (lane >> 4) * 8;
    const int lb = lane & 15;
    const int bOff = (wn * 32 + (lb & 7)) * TW + ((lb >> 3) & 1) * 8;

    {
        __nv_bfloat16* s = smx;
#pragma unroll
        for (int p = 0; p < 2; ++p) {
            int row = r0 + p * 64;
            size_t ga = (size_t)(bm + row) * K + c0;
            size_t gw = (size_t)(bn + row) * K + c0;
            int so = row * TW + c0;
            cpa16_ca(s + 0 * PL + so, Ah + ga);
            cpa16_ca(s + 1 * PL + so, Al + ga);
            cpa16_cg(s + 2 * PL + so, Wh + gw);
            cpa16_cg(s + 3 * PL + so, Wl + gw);
        }
        cpa_commit();
    }

    for (int kt = 0; kt < nk; ++kt) {
        cpa_wait0();
        __syncthreads();

        if (kt + 1 < nk) {
            __nv_bfloat16* s = smx + ((kt + 1) & 1) * GBUF;
            int k0 = (kt + 1) * 32;
#pragma unroll
            for (int p = 0; p < 2; ++p) {
                int row = r0 + p * 64;
                size_t ga = (size_t)(bm + row) * K + k0 + c0;
                size_t gw = (size_t)(bn + row) * K + k0 + c0;
                int so = row * TW + c0;
                cpa16_ca(s + 0 * PL + so, Ah + ga);
                cpa16_ca(s + 1 * PL + so, Al + ga);
                cpa16_cg(s + 2 * PL + so, Wh + gw);
                cpa16_cg(s + 3 * PL + so, Wl + gw);
            }
            cpa_commit();
        }

        const __nv_bfloat16* sb = smx + (kt & 1) * GBUF;

#pragma unroll
        for (int ks = 0; ks < 2; ++ks) {
            unsigned aH[4][4], aL[4][4], bH[4][2], bL[4][2];
#pragma unroll
            for (int i = 0; i < 4; ++i) {
                int off = aOff + i * 16 * TW + ks * 16;
                ldsm4(aH[i], sb + 0 * PL + off);
                ldsm4(aL[i], sb + 1 * PL + off);
            }
#pragma unroll
            for (int j = 0; j < 4; ++j) {
                int off = bOff + j * 8 * TW + ks * 16;
                ldsm2(bH[j], sb + 2 * PL + off);
                ldsm2(bL[j], sb + 3 * PL + off);
            }
            // Pass-outer ordering: consecutive mma hit different accumulators
#pragma unroll
            for (int i = 0; i < 4; ++i)
#pragma unroll
                for (int j = 0; j < 4; ++j)
                    mma_bf16(acc[i][j], aH[i], bH[j]);
#pragma unroll
            for (int i = 0; i < 4; ++i)
#pragma unroll
                for (int j = 0; j < 4; ++j)
                    mma_bf16(acc[i][j], aH[i], bL[j]);
#pragma unroll
            for (int i = 0; i < 4; ++i)
#pragma unroll
                for (int j = 0; j < 4; ++j)
                    mma_bf16(acc[i][j], aL[i], bH[j]);
        }
    }

#pragma unroll
    for (int i = 0; i < 4; ++i) {
        int row0 = bm + wm * 64 + i * 16 + g;
#pragma unroll
        for (int j = 0; j < 4; ++j) {
            int col = bn + wn * 32 + j * 8 + t * 2;
            float b0 = bias[col], b1 = bias[col + 1];
            float v00 = acc[i][j][0] + b0, v01 = acc[i][j][1] + b1;
            float v10 = acc[i][j][2] + b0, v11 = acc[i][j][3] + b1;
            if (CH) {
                size_t p0 = (size_t)row0 * N + col;
                size_t p1 = (size_t)(row0 + 8) * N + col;
                __nv_bfloat16 h00 = __float2bfloat16(v00), h01 = __float2bfloat16(v01);
                __nv_bfloat16 h10 = __float2bfloat16(v10), h11 = __float2bfloat16(v11);
                *(__nv_bfloat162*)(CH + p0) = __nv_bfloat162(h00, h01);
                *(__nv_bfloat162*)(CH + p1) = __nv_bfloat162(h10, h11);
                *(__nv_bfloat162*)(CL + p0) = __nv_bfloat162(
                    __float2bfloat16(v00 - __bfloat162float(h00)),
                    __float2bfloat16(v01 - __bfloat162float(h01)));
                *(__nv_bfloat162*)(CL + p1) = __nv_bfloat162(
                    __float2bfloat16(v10 - __bfloat162float(h10)),
                    __float2bfloat16(v11 - __bfloat162float(h11)));
            } else {
                *(float2*)(C + (size_t)row0 * N + col) = make_float2(v00, v01);
                *(float2*)(C + (size_t)(row0 + 8) * N + col) = make_float2(v10, v11);
            }
        }
    }
}

// ---------------------------------------------------------------------------
// Persistent tensor-core bidirectional GRU layer (R7 protocol, MUFU gates,
// pass-outer mma ordering, depth-2 h-fragment prefetch, dir anti-phase
// stagger). 256 blocks (128/dir), 8 units/block, 2 CTAs/SM.
// ---------------------------------------------------------------------------
constexpr int WSL_U32 = 3 * 64 * 32 * 2;
constexpr int REC_SMEM = WSL_U32 * 4 + (8 * 3 * 32 * 4) * 4;

__device__ __forceinline__ unsigned ld_acquire(const unsigned* p) {
    unsigned v;
    asm volatile("ld.global.acquire.gpu.u32 %0, [%1];" : "=r"(v) : "l"(p) : "memory");
    return v;
}
__device__ __forceinline__ void red_release_add(unsigned* p, unsigned v) {
    asm volatile("red.release.gpu.global.add.u32 [%0], %1;" :: "l"(p), "r"(v) : "memory");
}
__device__ __forceinline__ float fast_sigmoid(float x) {
    return 1.f / (1.f + __expf(-x));
}
__device__ __forceinline__ float fast_tanh(float x) {
    float e = __expf(2.f * x);
    return (e - 1.f) / (e + 1.f);
}

__global__ void __launch_bounds__(256, 2) gru_layer_tc_kernel(
    const unsigned* __restrict__ WFH, const unsigned* __restrict__ WFL,
    const float* __restrict__ bhh,
    const float* __restrict__ gx,
    __nv_bfloat16* __restrict__ YH, __nv_bfloat16* __restrict__ YL,
    unsigned* __restrict__ HF,
    unsigned* __restrict__ bar)
{
    extern __shared__ unsigned smu[];
    unsigned* wsL = smu;
    float* red = (float*)(smu + WSL_U32);

    const int tid  = threadIdx.x;
    const int dir  = blockIdx.x >> 7;
    const int blk  = blockIdx.x & 127;
    const int B16  = blk >> 1;
    const int half = blk & 1;
    const int u0   = blk * 8;
    const int lane = tid & 31, w = tid >> 5;
    unsigned* bard = bar + dir * 32;

    {
        const unsigned* lbase = WFL + (size_t)(dir * 64 + B16) * (6 * 4096);
#pragma unroll
        for (int t = 0; t < 3; ++t) {
            const uint4* src = (const uint4*)(lbase + (t * 2 + half) * 4096);
            uint4* dst = (uint4*)(wsL + t * 4096);
            for (int i = tid; i < 1024; i += 256) dst[i] = src[i];
        }
    }

    unsigned bHreg[8][3][2];
    {
        const unsigned* hbase = WFH + (size_t)(dir * 64 + B16) * (6 * 4096);
#pragma unroll
        for (int kk = 0; kk < 8; ++kk) {
            int ks = w * 8 + kk;
#pragma unroll
            for (int t = 0; t < 3; ++t) {
                uint2 v = *(const uint2*)(hbase + (t * 2 + half) * 4096 + ks * 64 + lane * 2);
                bHreg[kk][t][0] = v.x;
                bHreg[kk][t][1] = v.y;
            }
        }
    }

    const bool gactive = tid < 128;
    const int gb = tid >> 3;
    const int gu = tid & 7;
    const int gj = u0 + gu;
    float br = 0.f, bz = 0.f, bn2 = 0.f;
    if (gactive) {
        br  = bhh[dir * 3072 + gj];
        bz  = bhh[dir * 3072 + 1024 + gj];
        bn2 = bhh[dir * 3072 + 2048 + gj];
    }
    float hprev = 0.f;

    const int ksb   = blk >> 1;
    const int wlane = ((gb & 7) << 2) + (gu >> 1);
    const int wreg  = (half ? 2 : 0) + ((gb >= 8) ? 1 : 0);
    const int widx  = (ksb * 32 + wlane) * 4 + wreg;
    const int foff  = wlane * 4 + (gu & 1) + ((gb >= 8) ? 2 : 0);

    float xr = 0.f, xz = 0.f, xn = 0.f;
    if (gactive) {
        int tt0 = dir ? (Tt - 1) : 0;
        const float* gxp = gx + (size_t)(tt0 * 16 + gb) * 6144 + dir * 3072;
        xr = __ldg(gxp + gj);
        xz = __ldg(gxp + 1024 + gj);
        xn = __ldg(gxp + 2048 + gj);
    }

    __syncthreads();

    // Anti-phase stagger: delay dir-1 blocks by ~half a step so the two
    // directions' mma phases interleave with each other's gate+barrier idle
    // on shared SMs. One-time, deterministic output, self-stabilizing.
    if (dir == 1) {
        long long t0 = clock64();
        while (clock64() - t0 < 1500) { }
    }
    __syncthreads();

    for (int s = 0; s < Tt; ++s) {
        const int cur = s & 1, nxt = cur ^ 1;
        const int tt  = dir ? (Tt - 1 - s) : s;

        float acc[3][4];
#pragma unroll
        for (int t = 0; t < 3; ++t)
#pragma unroll
            for (int q = 0; q < 4; ++q) acc[t][q] = 0.f;

        const unsigned* hfH = HF + ((size_t)(cur * 2 + dir) * 2 + 0) * 8192;
        const unsigned* hfL = HF + ((size_t)(cur * 2 + dir) * 2 + 1) * 8192;

        // Depth-2 software prefetch on h fragments
        uint4 AHv = __ldcg((const uint4*)(hfH + ((w * 8) * 32 + lane) * 4));
        uint4 ALv = __ldcg((const uint4*)(hfL + ((w * 8) * 32 + lane) * 4));

#pragma unroll
        for (int kk = 0; kk < 8; ++kk) {
            unsigned aH[4] = {AHv.x, AHv.y, AHv.z, AHv.w};
            unsigned aL[4] = {ALv.x, ALv.y, ALv.z, ALv.w};
            if (kk < 7) {
                int ksn = w * 8 + kk + 1;
                AHv = __ldcg((const uint4*)(hfH + (ksn * 32 + lane) * 4));
                ALv = __ldcg((const uint4*)(hfL + (ksn * 32 + lane) * 4));
            }
            int ks = w * 8 + kk;
            // Pass-outer ordering: consecutive mma hit different acc[t]
#pragma unroll
            for (int t = 0; t < 3; ++t)
                mma_bf16(acc[t], aH, bHreg[kk][t]);
#pragma unroll
            for (int t = 0; t < 3; ++t)
                mma_bf16(acc[t], aL, bHreg[kk][t]);
#pragma unroll
            for (int t = 0; t < 3; ++t) {
                uint2 bLv = *(const uint2*)&wsL[t * 4096 + ks * 64 + lane * 2];
                unsigned bL[2] = {bLv.x, bLv.y};
                mma_bf16(acc[t], aH, bL);
            }
        }
#pragma unroll
        for (int t = 0; t < 3; ++t)
            *(float4*)&red[((w * 3 + t) * 32 + lane) * 4] =
                make_float4(acc[t][0], acc[t][1], acc[t][2], acc[t][3]);
        __syncthreads();

        if (gactive) {
            float ghr = br, ghz = bz, ghn = bn2;
#pragma unroll
            for (int ww = 0; ww < 8; ++ww) {
                ghr += red[(ww * 3 + 0) * 128 + foff];
                ghz += red[(ww * 3 + 1) * 128 + foff];
                ghn += red[(ww * 3 + 2) * 128 + foff];
            }
            float r = fast_sigmoid(xr + ghr);
            float z = fast_sigmoid(xz + ghz);
            float n = fast_tanh(xn + r * ghn);
            float hnew = (1.f - z) * n + z * hprev;
            hprev = hnew;

            __nv_bfloat16 hhi = __float2bfloat16(hnew);
            float rlo = hnew - __bfloat162float(hhi);
            __nv_bfloat16 hlo = __float2bfloat16(rlo);
            unsigned vh = (unsigned)__bfloat16_as_ushort(hhi);
            unsigned vl = (unsigned)__bfloat16_as_ushort(hlo);
            unsigned phh = __shfl_down_sync(0xffffffffu, vh, 1);
            unsigned pll = __shfl_down_sync(0xffffffffu, vl, 1);
            if ((gu & 1) == 0) {
                unsigned hp = (phh << 16) | vh;
                unsigned lp = (pll << 16) | vl;
                unsigned* oH = HF + ((size_t)(nxt * 2 + dir) * 2 + 0) * 8192;
                unsigned* oL = HF + ((size_t)(nxt * 2 + dir) * 2 + 1) * 8192;
                oH[widx] = hp;
                oL[widx] = lp;
                size_t yi = (size_t)(tt * 16 + gb) * 1024 + dir * 512 + (gj >> 1);
                ((unsigned*)YH)[yi] = hp;
                ((unsigned*)YL)[yi] = lp;
            }

            if (s + 1 < Tt) {
                int ttn = dir ? (Tt - 2 - s) : (s + 1);
                const float* gxn = gx + (size_t)(ttn * 16 + gb) * 6144 + dir * 3072;
                xr = __ldg(gxn + gj);
                xz = __ldg(gxn + 1024 + gj);
                xn = __ldg(gxn + 2048 + gj);
            }
        }

        __syncthreads();
        if (tid == 0) {
            red_release_add(bard, 1u);
            unsigned tgt = (unsigned)(s + 1) * 128;
            while (ld_acquire(bard) < tgt) { }
        }
        __syncthreads();
    }
}

// ---------------------------------------------------------------------------
extern "C" void kernel_launch(void* const* d_in, const int* in_sizes, int n_in,
                              void* d_out, int out_size)
{
    const float* inp     = (const float*)d_in[0];
    const float* w_in    = (const float*)d_in[1];
    const float* b_in    = (const float*)d_in[2];
    const float* w_ih_l0 = (const float*)d_in[3];
    const float* w_hh_l0 = (const float*)d_in[4];
    const float* b_ih_l0 = (const float*)d_in[5];
    const float* b_hh_l0 = (const float*)d_in[6];
    const float* w_ih_l1 = (const float*)d_in[7];
    const float* w_hh_l1 = (const float*)d_in[8];
    const float* b_ih_l1 = (const float*)d_in[9];
    const float* b_hh_l1 = (const float*)d_in[10];
    const float* w_out   = (const float*)d_in[11];
    const float* b_out   = (const float*)d_in[12];
    float* out = (float*)d_out;

    float* S = nullptr;
    cudaGetSymbolAddress((void**)&S, g_scratch);
    __nv_bfloat16* BF = nullptr;
    cudaGetSymbolAddress((void**)&BF, g_bf);

    float* GX0  = S + OFF_GX0;
    float* GX1  = S + OFF_GX1;
    float* OUTT = S + OFF_OUTT;
    unsigned* WFH0 = (unsigned*)(S + OFF_WFH0);
    unsigned* WFL0 = (unsigned*)(S + OFF_WFL0);
    unsigned* WFH1 = (unsigned*)(S + OFF_WFH1);
    unsigned* WFL1 = (unsigned*)(S + OFF_WFL1);
    unsigned* HF0  = (unsigned*)(S + OFF_HF0);
    unsigned* HF1  = (unsigned*)(S + OFF_HF1);
    unsigned* BAR0 = (unsigned*)(S + OFF_BAR0);
    unsigned* BAR1 = (unsigned*)(S + OFF_BAR1);

    cudaFuncSetAttribute(gemm_bf16_split_kernel,
                         cudaFuncAttributeMaxDynamicSharedMemorySize, SMEM_GEMM);
    cudaFuncSetAttribute(gru_layer_tc_kernel,
                         cudaFuncAttributeMaxDynamicSharedMemorySize, REC_SMEM);

    const int M = Tt * Bb;  // 8192

    // 1) Mega-prep
    prep_kernel<<<NB_PREP, 256>>>(inp, w_in, w_ih_l0, w_ih_l1, w_out,
                                  w_hh_l0, w_hh_l1, BF,
                                  WFH0, WFL0, WFH1, WFL1, HF0, HF1, BAR0, BAR1);

    // 2) Input projection (bf16 split output)
    gemm_bf16_split_kernel<<<dim3(F / 128, M / 128), 256, SMEM_GEMM>>>(
        BF + BOFF_XH, BF + BOFF_XL, BF + BOFF_WINH, BF + BOFF_WINL, b_in,
        nullptr, BF + BOFF_H0H, BF + BOFF_H0L, M, F, INP);

    // 3) Layer 0 gx
    gemm_bf16_split_kernel<<<dim3(6 * F / 128, M / 128), 256, SMEM_GEMM>>>(
        BF + BOFF_H0H, BF + BOFF_H0L, BF + BOFF_WI0H, BF + BOFF_WI0L, b_ih_l0,
        GX0, nullptr, nullptr, M, 6 * F, F);

    // 4) Layer 0 recurrence  <-- ncu capture slot
    gru_layer_tc_kernel<<<256, 256, REC_SMEM>>>(
        WFH0, WFL0, b_hh_l0, GX0, BF + BOFF_Y0H, BF + BOFF_Y0L, HF0, BAR0);

    // 5) Layer 1 gx
    gemm_bf16_split_kernel<<<dim3(6 * F / 128, M / 128), 256, SMEM_GEMM>>>(
        BF + BOFF_Y0H, BF + BOFF_Y0L, BF + BOFF_WI1H, BF + BOFF_WI1L, b_ih_l1,
        GX1, nullptr, nullptr, M, 6 * F, 2 * F);

    // 6) Layer 1 recurrence
    gru_layer_tc_kernel<<<256, 256, REC_SMEM>>>(
        WFH1, WFL1, b_hh_l1, GX1, BF + BOFF_Y1H, BF + BOFF_Y1L, HF1, BAR1);

    // 7) Output projection
    gemm_bf16_split_kernel<<<dim3(OUTD / 128, M / 128), 256, SMEM_GEMM>>>(
        BF + BOFF_Y1H, BF + BOFF_Y1L, BF + BOFF_WOH, BF + BOFF_WOL, b_out,
        OUTT, nullptr, nullptr, M, OUTD, 2 * F);

    // 8) Final transpose
    transpose_out_kernel<<<dim3(Tt / 32, OUTD / 32, Bb), dim3(32, 8)>>>(OUTT, out);
}